// round 1
// baseline (speedup 1.0000x reference)
#include <cuda_runtime.h>

// ---------------------------------------------------------------------------
// SwinV2 block: B=32, H=W=64, C=256, NH=8, HD=32, WS=8, SS=4
// Round 0: all-fp32 baseline. Fused shift/window-partition into GEMM gather,
// fused reverse into proj scatter. Tiled 128x64x16 fp32 GEMM.
// ---------------------------------------------------------------------------

static constexpr int Bc      = 32;
static constexpr int HWc     = 64;
static constexpr int Cc      = 256;
static constexpr int NHc     = 8;
static constexpr int HDc     = 32;
static constexpr int WSc     = 8;
static constexpr int SSc     = 4;
static constexpr int NTOK    = 64;       // tokens per window
static constexpr int MROWS   = 131072;   // B * 64 * 64
static constexpr int HIDc    = 1024;

// Scratch (device globals: no allocation allowed)
__device__ float g_qkv [(size_t)MROWS * 768];
__device__ float g_attn[(size_t)MROWS * Cc];
__device__ float g_y   [(size_t)MROWS * Cc];
__device__ float g_x1  [(size_t)MROWS * Cc];
__device__ float g_h   [(size_t)MROWS * HIDc];
__device__ float g_h2  [(size_t)MROWS * Cc];
__device__ float g_rpb [NHc * NTOK * NTOK];   // 16*sigmoid(cpb) per head
__device__ float g_qkvbias[768];
__device__ float g_hscale[NHc];
__device__ int   g_rowmap[MROWS];

__device__ __forceinline__ float gelu_f(float x) {
    float x3 = x * x * x;
    return 0.5f * x * (1.f + tanhf(0.7978845608028654f * (x + 0.044715f * x3)));
}

// ---------------------------------------------------------------------------
// prep: qkv bias concat, head scales, CPB MLP -> rpb table (16*sigmoid)
// single block, 256 threads
// ---------------------------------------------------------------------------
__global__ void prep_kernel(const float* __restrict__ logit_scale,
                            const float* __restrict__ cpb_w1,
                            const float* __restrict__ cpb_b1,
                            const float* __restrict__ cpb_w2,
                            const float* __restrict__ q_bias,
                            const float* __restrict__ v_bias) {
    __shared__ float table[225][NHc];
    int t = threadIdx.x;

    for (int i = t; i < 768; i += 256) {
        float v = 0.f;
        if (i < 256)       v = q_bias[i];
        else if (i >= 512) v = v_bias[i - 512];
        g_qkvbias[i] = v;
    }
    if (t < NHc) {
        float ls = logit_scale[t];
        g_hscale[t] = expf(fminf(ls, 4.605170185988092f)); // log(100)
    }
    if (t < 225) {
        int a = t / 15, b = t % 15;
        float f0 = (float)(a - 7) * (8.f / 7.f);
        float f1 = (float)(b - 7) * (8.f / 7.f);
        // sign(t)*log2(|t|+1)/log2(8)
        f0 = copysignf(log2f(fabsf(f0) + 1.f) * (1.f / 3.f), f0);
        f1 = copysignf(log2f(fabsf(f1) + 1.f) * (1.f / 3.f), f1);
        float acc[NHc];
        #pragma unroll
        for (int h = 0; h < NHc; h++) acc[h] = 0.f;
        for (int j = 0; j < 512; j++) {
            float hid = f0 * cpb_w1[j] + f1 * cpb_w1[512 + j] + cpb_b1[j];
            hid = fmaxf(hid, 0.f);
            #pragma unroll
            for (int h = 0; h < NHc; h++) acc[h] += hid * cpb_w2[j * NHc + h];
        }
        #pragma unroll
        for (int h = 0; h < NHc; h++) table[t][h] = acc[h];
    }
    __syncthreads();
    for (int idx = t; idx < NHc * NTOK * NTOK; idx += 256) {
        int h = idx >> 12, rem = idx & 4095, i = rem >> 6, j = rem & 63;
        int iy = i >> 3, ix = i & 7, jy = j >> 3, jx = j & 7;
        int ti = (iy - jy + 7) * 15 + (ix - jx + 7);
        float v = table[ti][h];
        g_rpb[idx] = 16.f / (1.f + expf(-v));
    }
}

// row r = (b, window w, token n) -> gather/scatter index into (B, H*W) grid
__global__ void rowmap_kernel() {
    int r = blockIdx.x * 256 + threadIdx.x;
    if (r >= MROWS) return;
    int b = r >> 12;
    int rem = r & 4095;
    int w = rem >> 6, n = rem & 63;
    int wy = w >> 3, wx = w & 7, ty = n >> 3, tx = n & 7;
    int hs = (wy * 8 + ty + SSc) & 63;
    int ws = (wx * 8 + tx + SSc) & 63;
    g_rowmap[r] = (b << 12) + (hs << 6) + ws;
}

// ---------------------------------------------------------------------------
// Tiled fp32 GEMM: C[M,N] = A[M,K] @ B[K,N] + bias (+gelu)
// BM=128, BN=64, BK=16, 256 threads, 8x4 per-thread tile.
// Optional A-row gather and C-row scatter (both via g-rowmap argument).
// M is always 131072 (multiple of 128); N multiple of 64; K multiple of 16.
// ---------------------------------------------------------------------------
template<bool GELU, bool GATHER_A, bool SCATTER_C>
__global__ __launch_bounds__(256)
void gemm_kernel(const float* __restrict__ A, const float* __restrict__ Bm,
                 const float* __restrict__ bias, float* __restrict__ Cm,
                 int N, int K, const int* __restrict__ rowmap) {
    __shared__ float As[16][128];
    __shared__ float Bs[16][64];
    const int t  = threadIdx.x;
    const int tx = t & 15, ty = t >> 4;
    const int m0 = blockIdx.y * 128, n0 = blockIdx.x * 64;

    int ra = m0 + (t >> 2);
    int r0 = GATHER_A ? rowmap[ra]      : ra;
    int r1 = GATHER_A ? rowmap[ra + 64] : ra + 64;
    const float* arow0 = A + (size_t)r0 * K + ((t & 3) << 2);
    const float* arow1 = A + (size_t)r1 * K + ((t & 3) << 2);
    const float* brow  = Bm + (size_t)(t >> 4) * N + n0 + ((t & 15) << 2);

    float acc[8][4];
    #pragma unroll
    for (int i = 0; i < 8; i++)
        #pragma unroll
        for (int j = 0; j < 4; j++) acc[i][j] = 0.f;

    for (int k0 = 0; k0 < K; k0 += 16) {
        float4 a0 = *(const float4*)(arow0 + k0);
        float4 a1 = *(const float4*)(arow1 + k0);
        float4 b0 = *(const float4*)(brow + (size_t)k0 * N);
        __syncthreads();
        int rr = t >> 2, cc = (t & 3) << 2;
        As[cc + 0][rr] = a0.x; As[cc + 1][rr] = a0.y;
        As[cc + 2][rr] = a0.z; As[cc + 3][rr] = a0.w;
        As[cc + 0][rr + 64] = a1.x; As[cc + 1][rr + 64] = a1.y;
        As[cc + 2][rr + 64] = a1.z; As[cc + 3][rr + 64] = a1.w;
        *(float4*)&Bs[t >> 4][(t & 15) << 2] = b0;
        __syncthreads();
        #pragma unroll
        for (int kk = 0; kk < 16; kk++) {
            float4 av0 = *(const float4*)&As[kk][ty << 3];
            float4 av1 = *(const float4*)&As[kk][(ty << 3) + 4];
            float4 bv  = *(const float4*)&Bs[kk][tx << 2];
            float am[8] = {av0.x, av0.y, av0.z, av0.w, av1.x, av1.y, av1.z, av1.w};
            float bb[4] = {bv.x, bv.y, bv.z, bv.w};
            #pragma unroll
            for (int i = 0; i < 8; i++)
                #pragma unroll
                for (int j = 0; j < 4; j++) acc[i][j] += am[i] * bb[j];
        }
    }

    float bv0 = bias[n0 + (tx << 2) + 0];
    float bv1 = bias[n0 + (tx << 2) + 1];
    float bv2 = bias[n0 + (tx << 2) + 2];
    float bv3 = bias[n0 + (tx << 2) + 3];
    #pragma unroll
    for (int i = 0; i < 8; i++) {
        int r  = m0 + (ty << 3) + i;
        int rc = SCATTER_C ? rowmap[r] : r;
        float4 o;
        o.x = acc[i][0] + bv0; o.y = acc[i][1] + bv1;
        o.z = acc[i][2] + bv2; o.w = acc[i][3] + bv3;
        if (GELU) { o.x = gelu_f(o.x); o.y = gelu_f(o.y); o.z = gelu_f(o.z); o.w = gelu_f(o.w); }
        *(float4*)(Cm + (size_t)rc * N + n0 + (tx << 2)) = o;
    }
}

// ---------------------------------------------------------------------------
// Windowed cosine attention: one block per (window, head). 256 threads.
// ---------------------------------------------------------------------------
__global__ __launch_bounds__(256)
void attn_kernel(const float* __restrict__ qkv, float* __restrict__ out) {
    __shared__ float qs[64][33];
    __shared__ float ks[64][33];
    __shared__ float vs[64][33];
    __shared__ float Ss[64][65];
    __shared__ int lab[64];
    const int t  = threadIdx.x;
    const int b_ = blockIdx.x >> 3, h = blockIdx.x & 7;

    const float* base = qkv + (size_t)b_ * (64 * 768) + h * 32;
    #pragma unroll
    for (int r = 0; r < 8; r++) {
        int idx = r * 256 + t;
        int n = idx >> 5, d = idx & 31;
        const float* p = base + n * 768 + d;
        qs[n][d] = p[0];
        ks[n][d] = p[256];
        vs[n][d] = p[512];
    }
    if (t < 64) {
        int w = b_ & 63;
        int wy = w >> 3, wx = w & 7, ty_ = t >> 3, tx_ = t & 7;
        int gh = wy * 8 + ty_, gw = wx * 8 + tx_;
        int rh = gh < 56 ? 0 : (gh < 60 ? 1 : 2);
        int rw = gw < 56 ? 0 : (gw < 60 ? 1 : 2);
        lab[t] = rh * 3 + rw;
    }
    __syncthreads();

    // L2-normalize q and k rows (4 lanes per row)
    {
        int row = t >> 2, sl = (t & 3) << 3;
        float s = 0.f;
        #pragma unroll
        for (int dd = 0; dd < 8; dd++) { float v = qs[row][sl + dd]; s += v * v; }
        s += __shfl_xor_sync(0xffffffffu, s, 1);
        s += __shfl_xor_sync(0xffffffffu, s, 2);
        float rn = rsqrtf(fmaxf(s, 1e-12f));
        #pragma unroll
        for (int dd = 0; dd < 8; dd++) qs[row][sl + dd] *= rn;
        s = 0.f;
        #pragma unroll
        for (int dd = 0; dd < 8; dd++) { float v = ks[row][sl + dd]; s += v * v; }
        s += __shfl_xor_sync(0xffffffffu, s, 1);
        s += __shfl_xor_sync(0xffffffffu, s, 2);
        rn = rsqrtf(fmaxf(s, 1e-12f));
        #pragma unroll
        for (int dd = 0; dd < 8; dd++) ks[row][sl + dd] *= rn;
    }
    __syncthreads();

    // S = qn @ knT * scale + rpb + mask   (4x4 per thread)
    {
        const int i0 = (t >> 4) << 2, j0 = (t & 15) << 2;
        float accS[4][4];
        #pragma unroll
        for (int a = 0; a < 4; a++)
            #pragma unroll
            for (int b = 0; b < 4; b++) accS[a][b] = 0.f;
        for (int d = 0; d < 32; d++) {
            float qv[4], kv[4];
            #pragma unroll
            for (int c = 0; c < 4; c++) { qv[c] = qs[i0 + c][d]; kv[c] = ks[j0 + c][d]; }
            #pragma unroll
            for (int a = 0; a < 4; a++)
                #pragma unroll
                for (int b = 0; b < 4; b++) accS[a][b] += qv[a] * kv[b];
        }
        const float sc = g_hscale[h];
        const float* rp = g_rpb + h * 4096;
        #pragma unroll
        for (int a = 0; a < 4; a++)
            #pragma unroll
            for (int b = 0; b < 4; b++) {
                int i = i0 + a, j = j0 + b;
                float mval = (lab[i] == lab[j]) ? 0.f : -100.f;
                Ss[i][j] = accS[a][b] * sc + rp[i * 64 + j] + mval;
            }
    }
    __syncthreads();

    // softmax per row (4 lanes per row, 16 cols each)
    {
        int row = t >> 2, sl = (t & 3) << 4;
        float mx = -1e30f;
        float ev[16];
        #pragma unroll
        for (int jj = 0; jj < 16; jj++) mx = fmaxf(mx, Ss[row][sl + jj]);
        mx = fmaxf(mx, __shfl_xor_sync(0xffffffffu, mx, 1));
        mx = fmaxf(mx, __shfl_xor_sync(0xffffffffu, mx, 2));
        float sm = 0.f;
        #pragma unroll
        for (int jj = 0; jj < 16; jj++) { ev[jj] = expf(Ss[row][sl + jj] - mx); sm += ev[jj]; }
        sm += __shfl_xor_sync(0xffffffffu, sm, 1);
        sm += __shfl_xor_sync(0xffffffffu, sm, 2);
        float inv = 1.f / sm;
        #pragma unroll
        for (int jj = 0; jj < 16; jj++) Ss[row][sl + jj] = ev[jj] * inv;
    }
    __syncthreads();

    // O = P @ V  (4x4 per thread, 128 active threads)
    if (t < 128) {
        const int i0 = (t >> 3) << 2, d0 = (t & 7) << 2;
        float accO[4][4];
        #pragma unroll
        for (int a = 0; a < 4; a++)
            #pragma unroll
            for (int b = 0; b < 4; b++) accO[a][b] = 0.f;
        for (int j = 0; j < 64; j++) {
            float pv[4], vv[4];
            #pragma unroll
            for (int c = 0; c < 4; c++) { pv[c] = Ss[i0 + c][j]; vv[c] = vs[j][d0 + c]; }
            #pragma unroll
            for (int a = 0; a < 4; a++)
                #pragma unroll
                for (int b = 0; b < 4; b++) accO[a][b] += pv[a] * vv[b];
        }
        #pragma unroll
        for (int a = 0; a < 4; a++)
            #pragma unroll
            for (int b = 0; b < 4; b++)
                out[(size_t)(b_ * 64 + i0 + a) * 256 + h * 32 + d0 + b] = accO[a][b];
    }
}

// ---------------------------------------------------------------------------
// out = resid + LayerNorm(y) * scale + bias   (warp per row, C=256)
// ---------------------------------------------------------------------------
__global__ __launch_bounds__(256)
void ln_add_kernel(const float* __restrict__ resid, const float* __restrict__ y,
                   const float* __restrict__ sc, const float* __restrict__ bi,
                   float* __restrict__ out) {
    int warp = (blockIdx.x * 256 + threadIdx.x) >> 5;
    int lane = threadIdx.x & 31;
    if (warp >= MROWS) return;
    const float* yr = y + (size_t)warp * 256;
    float v[8];
    #pragma unroll
    for (int i = 0; i < 8; i++) v[i] = yr[lane * 8 + i];
    float s = 0.f;
    #pragma unroll
    for (int i = 0; i < 8; i++) s += v[i];
    #pragma unroll
    for (int o = 16; o > 0; o >>= 1) s += __shfl_xor_sync(0xffffffffu, s, o);
    float mean = s * (1.f / 256.f);
    float sq = 0.f;
    #pragma unroll
    for (int i = 0; i < 8; i++) { float d = v[i] - mean; sq += d * d; }
    #pragma unroll
    for (int o = 16; o > 0; o >>= 1) sq += __shfl_xor_sync(0xffffffffu, sq, o);
    float rstd = rsqrtf(sq * (1.f / 256.f) + 1e-6f);
    const float* rr = resid + (size_t)warp * 256;
    float* op = out + (size_t)warp * 256;
    #pragma unroll
    for (int i = 0; i < 8; i++) {
        int c = lane * 8 + i;
        op[c] = rr[c] + (v[i] - mean) * rstd * sc[c] + bi[c];
    }
}

// ---------------------------------------------------------------------------
extern "C" void kernel_launch(void* const* d_in, const int* in_sizes, int n_in,
                              void* d_out, int out_size) {
    const float* x       = (const float*)d_in[0];
    const float* qkv_w   = (const float*)d_in[1];
    const float* q_bias  = (const float*)d_in[2];
    const float* v_bias  = (const float*)d_in[3];
    const float* lscale  = (const float*)d_in[4];
    const float* cpb_w1  = (const float*)d_in[5];
    const float* cpb_b1  = (const float*)d_in[6];
    const float* cpb_w2  = (const float*)d_in[7];
    const float* proj_w  = (const float*)d_in[8];
    const float* proj_b  = (const float*)d_in[9];
    const float* n1s     = (const float*)d_in[10];
    const float* n1b     = (const float*)d_in[11];
    const float* n2s     = (const float*)d_in[12];
    const float* n2b     = (const float*)d_in[13];
    const float* fc1_w   = (const float*)d_in[14];
    const float* fc1_b   = (const float*)d_in[15];
    const float* fc2_w   = (const float*)d_in[16];
    const float* fc2_b   = (const float*)d_in[17];
    float* out = (float*)d_out;

    void *p_qkv, *p_attn, *p_y, *p_x1, *p_h, *p_h2, *p_qb, *p_rm;
    cudaGetSymbolAddress(&p_qkv,  g_qkv);
    cudaGetSymbolAddress(&p_attn, g_attn);
    cudaGetSymbolAddress(&p_y,    g_y);
    cudaGetSymbolAddress(&p_x1,   g_x1);
    cudaGetSymbolAddress(&p_h,    g_h);
    cudaGetSymbolAddress(&p_h2,   g_h2);
    cudaGetSymbolAddress(&p_qb,   g_qkvbias);
    cudaGetSymbolAddress(&p_rm,   g_rowmap);

    prep_kernel<<<1, 256>>>(lscale, cpb_w1, cpb_b1, cpb_w2, q_bias, v_bias);
    rowmap_kernel<<<512, 256>>>();

    // qkv = gather(x) @ qkv_w + qkv_bias
    gemm_kernel<false, true, false><<<dim3(768 / 64, MROWS / 128), 256>>>(
        x, qkv_w, (const float*)p_qb, (float*)p_qkv, 768, 256, (const int*)p_rm);

    // windowed attention
    attn_kernel<<<2048 * 8, 256>>>((const float*)p_qkv, (float*)p_attn);

    // y = scatter(attn @ proj_w + proj_b)
    gemm_kernel<false, false, true><<<dim3(256 / 64, MROWS / 128), 256>>>(
        (const float*)p_attn, proj_w, proj_b, (float*)p_y, 256, 256, (const int*)p_rm);

    // x1 = x + LN(y)
    ln_add_kernel<<<MROWS / 8, 256>>>(x, (const float*)p_y, n1s, n1b, (float*)p_x1);

    // h = gelu(x1 @ fc1_w + fc1_b)
    gemm_kernel<true, false, false><<<dim3(1024 / 64, MROWS / 128), 256>>>(
        (const float*)p_x1, fc1_w, fc1_b, (float*)p_h, 1024, 256, nullptr);

    // h2 = h @ fc2_w + fc2_b
    gemm_kernel<false, false, false><<<dim3(256 / 64, MROWS / 128), 256>>>(
        (const float*)p_h, fc2_w, fc2_b, (float*)p_h2, 256, 1024, nullptr);

    // out = x1 + LN(h2)
    ln_add_kernel<<<MROWS / 8, 256>>>((const float*)p_x1, (const float*)p_h2, n2s, n2b, out);
}

// round 2
// speedup vs baseline: 1.3819x; 1.3819x over previous
#include <cuda_runtime.h>

// ---------------------------------------------------------------------------
// SwinV2 block: B=32, H=W=64, C=256, NH=8, HD=32, WS=8, SS=4
// Round 1: TF32 tensor-core GEMMs (mma.sync.m16n8k8), fused gather/scatter.
// ---------------------------------------------------------------------------

static constexpr int SSc   = 4;
static constexpr int NTOK  = 64;
static constexpr int NHc   = 8;
static constexpr int Cc    = 256;
static constexpr int MROWS = 131072;
static constexpr int HIDc  = 1024;

__device__ float g_qkv [(size_t)MROWS * 768];
__device__ float g_attn[(size_t)MROWS * Cc];
__device__ float g_y   [(size_t)MROWS * Cc];
__device__ float g_x1  [(size_t)MROWS * Cc];
__device__ float g_h   [(size_t)MROWS * HIDc];
__device__ float g_h2  [(size_t)MROWS * Cc];
__device__ float g_rpb [NHc * NTOK * NTOK];
__device__ float g_qkvbias[768];
__device__ float g_hscale[NHc];
__device__ int   g_rowmap[MROWS];

__device__ __forceinline__ float gelu_f(float x) {
    float x3 = x * x * x;
    return 0.5f * x * (1.f + tanhf(0.7978845608028654f * (x + 0.044715f * x3)));
}

__device__ __forceinline__ unsigned f2tf32(float f) {
    unsigned u;
    asm("cvt.rna.tf32.f32 %0, %1;" : "=r"(u) : "f"(f));
    return u;
}

__device__ __forceinline__ void mma_tf32(float* c, const unsigned* a, const unsigned* b) {
    asm volatile(
        "mma.sync.aligned.m16n8k8.row.col.f32.tf32.tf32.f32 "
        "{%0,%1,%2,%3}, {%4,%5,%6,%7}, {%8,%9}, {%0,%1,%2,%3};"
        : "+f"(c[0]), "+f"(c[1]), "+f"(c[2]), "+f"(c[3])
        : "r"(a[0]), "r"(a[1]), "r"(a[2]), "r"(a[3]), "r"(b[0]), "r"(b[1]));
}

// ---------------------------------------------------------------------------
__global__ void prep_kernel(const float* __restrict__ logit_scale,
                            const float* __restrict__ cpb_w1,
                            const float* __restrict__ cpb_b1,
                            const float* __restrict__ cpb_w2,
                            const float* __restrict__ q_bias,
                            const float* __restrict__ v_bias) {
    __shared__ float table[225][NHc];
    int t = threadIdx.x;

    for (int i = t; i < 768; i += 256) {
        float v = 0.f;
        if (i < 256)       v = q_bias[i];
        else if (i >= 512) v = v_bias[i - 512];
        g_qkvbias[i] = v;
    }
    if (t < NHc) {
        float ls = logit_scale[t];
        g_hscale[t] = expf(fminf(ls, 4.605170185988092f));
    }
    if (t < 225) {
        int a = t / 15, b = t % 15;
        float f0 = (float)(a - 7) * (8.f / 7.f);
        float f1 = (float)(b - 7) * (8.f / 7.f);
        f0 = copysignf(log2f(fabsf(f0) + 1.f) * (1.f / 3.f), f0);
        f1 = copysignf(log2f(fabsf(f1) + 1.f) * (1.f / 3.f), f1);
        float acc[NHc];
        #pragma unroll
        for (int h = 0; h < NHc; h++) acc[h] = 0.f;
        for (int j = 0; j < 512; j++) {
            float hid = f0 * cpb_w1[j] + f1 * cpb_w1[512 + j] + cpb_b1[j];
            hid = fmaxf(hid, 0.f);
            #pragma unroll
            for (int h = 0; h < NHc; h++) acc[h] += hid * cpb_w2[j * NHc + h];
        }
        #pragma unroll
        for (int h = 0; h < NHc; h++) table[t][h] = acc[h];
    }
    __syncthreads();
    for (int idx = t; idx < NHc * NTOK * NTOK; idx += 256) {
        int h = idx >> 12, rem = idx & 4095, i = rem >> 6, j = rem & 63;
        int iy = i >> 3, ix = i & 7, jy = j >> 3, jx = j & 7;
        int ti = (iy - jy + 7) * 15 + (ix - jx + 7);
        float v = table[ti][h];
        g_rpb[idx] = 16.f / (1.f + expf(-v));
    }
}

__global__ void rowmap_kernel() {
    int r = blockIdx.x * 256 + threadIdx.x;
    if (r >= MROWS) return;
    int b = r >> 12;
    int rem = r & 4095;
    int w = rem >> 6, n = rem & 63;
    int wy = w >> 3, wx = w & 7, ty = n >> 3, tx = n & 7;
    int hs = (wy * 8 + ty + SSc) & 63;
    int ws = (wx * 8 + tx + SSc) & 63;
    g_rowmap[r] = (b << 12) + (hs << 6) + ws;
}

// ---------------------------------------------------------------------------
// TF32 GEMM: C[M,N] = A[M,K] @ B[K,N] + bias (+gelu)
// BM=128, BN=128, BK=16, 256 threads (8 warps, 2x4), warp tile 64x32.
// As[m][k] stride 20 (conflict-free frag LDS), Bs[k][n] stride 136.
// ---------------------------------------------------------------------------
#define AS_STRIDE 20
#define BS_STRIDE 136

template<bool GELU, bool GATHER_A, bool SCATTER_C>
__global__ __launch_bounds__(256)
void gemm_tf32(const float* __restrict__ A, const float* __restrict__ Bm,
               const float* __restrict__ bias, float* __restrict__ Cm,
               int N, int K, const int* __restrict__ rowmap) {
    __shared__ unsigned As[2][128 * AS_STRIDE];
    __shared__ unsigned Bs[2][16 * BS_STRIDE];

    const int t = threadIdx.x;
    const int lane = t & 31, wid = t >> 5;
    const int wm = (wid >> 2) << 6;   // 0 or 64
    const int wn = (wid & 3) << 5;    // 0,32,64,96
    const int m0 = blockIdx.y * 128, n0 = blockIdx.x * 128;

    // A loader: rows am, am+64 ; k chunk ak..ak+3
    const int am = t >> 2;
    const int ak = (t & 3) << 2;
    int r0 = m0 + am, r1 = m0 + am + 64;
    if (GATHER_A) { r0 = rowmap[r0]; r1 = rowmap[r1]; }
    const float* a0p = A + (size_t)r0 * K + ak;
    const float* a1p = A + (size_t)r1 * K + ak;
    // B loader: rows bk, bk+8 ; cols bn..bn+3
    const int bk = t >> 5;
    const int bn = (t & 31) << 2;
    const float* b0p = Bm + (size_t)bk * N + n0 + bn;
    const float* b1p = b0p + (size_t)8 * N;

    float acc[4][4][4];
    #pragma unroll
    for (int i = 0; i < 4; i++)
        #pragma unroll
        for (int j = 0; j < 4; j++)
            #pragma unroll
            for (int r = 0; r < 4; r++) acc[i][j][r] = 0.f;

    const int KT = K >> 4;
    float4 fa0 = *(const float4*)a0p;
    float4 fa1 = *(const float4*)a1p;
    float4 fb0 = *(const float4*)b0p;
    float4 fb1 = *(const float4*)b1p;

    int buf = 0;
    // store tile 0
    {
        uint4 u;
        u.x = f2tf32(fa0.x); u.y = f2tf32(fa0.y); u.z = f2tf32(fa0.z); u.w = f2tf32(fa0.w);
        *(uint4*)&As[0][am * AS_STRIDE + ak] = u;
        u.x = f2tf32(fa1.x); u.y = f2tf32(fa1.y); u.z = f2tf32(fa1.z); u.w = f2tf32(fa1.w);
        *(uint4*)&As[0][(am + 64) * AS_STRIDE + ak] = u;
        u.x = f2tf32(fb0.x); u.y = f2tf32(fb0.y); u.z = f2tf32(fb0.z); u.w = f2tf32(fb0.w);
        *(uint4*)&Bs[0][bk * BS_STRIDE + bn] = u;
        u.x = f2tf32(fb1.x); u.y = f2tf32(fb1.y); u.z = f2tf32(fb1.z); u.w = f2tf32(fb1.w);
        *(uint4*)&Bs[0][(bk + 8) * BS_STRIDE + bn] = u;
    }
    __syncthreads();

    for (int kt = 0; kt < KT; kt++) {
        if (kt + 1 < KT) {
            const float* ap0 = a0p + (kt + 1) * 16;
            const float* ap1 = a1p + (kt + 1) * 16;
            const float* bp0 = b0p + (size_t)(kt + 1) * 16 * N;
            const float* bp1 = b1p + (size_t)(kt + 1) * 16 * N;
            fa0 = *(const float4*)ap0;
            fa1 = *(const float4*)ap1;
            fb0 = *(const float4*)bp0;
            fb1 = *(const float4*)bp1;
        }

        const unsigned* Ab = As[buf];
        const unsigned* Bb = Bs[buf];
        #pragma unroll
        for (int ks = 0; ks < 2; ks++) {
            unsigned afrag[4][4], bfrag[4][2];
            const int kc = (ks << 3) + (lane & 3);
            #pragma unroll
            for (int mt = 0; mt < 4; mt++) {
                int mrow = wm + (mt << 4) + (lane >> 2);
                afrag[mt][0] = Ab[mrow * AS_STRIDE + kc];
                afrag[mt][1] = Ab[(mrow + 8) * AS_STRIDE + kc];
                afrag[mt][2] = Ab[mrow * AS_STRIDE + kc + 4];
                afrag[mt][3] = Ab[(mrow + 8) * AS_STRIDE + kc + 4];
            }
            #pragma unroll
            for (int nt = 0; nt < 4; nt++) {
                int ncol = wn + (nt << 3) + (lane >> 2);
                bfrag[nt][0] = Bb[kc * BS_STRIDE + ncol];
                bfrag[nt][1] = Bb[(kc + 4) * BS_STRIDE + ncol];
            }
            #pragma unroll
            for (int mt = 0; mt < 4; mt++)
                #pragma unroll
                for (int nt = 0; nt < 4; nt++)
                    mma_tf32(acc[mt][nt], afrag[mt], bfrag[nt]);
        }

        if (kt + 1 < KT) {
            int nb = buf ^ 1;
            uint4 u;
            u.x = f2tf32(fa0.x); u.y = f2tf32(fa0.y); u.z = f2tf32(fa0.z); u.w = f2tf32(fa0.w);
            *(uint4*)&As[nb][am * AS_STRIDE + ak] = u;
            u.x = f2tf32(fa1.x); u.y = f2tf32(fa1.y); u.z = f2tf32(fa1.z); u.w = f2tf32(fa1.w);
            *(uint4*)&As[nb][(am + 64) * AS_STRIDE + ak] = u;
            u.x = f2tf32(fb0.x); u.y = f2tf32(fb0.y); u.z = f2tf32(fb0.z); u.w = f2tf32(fb0.w);
            *(uint4*)&Bs[nb][bk * BS_STRIDE + bn] = u;
            u.x = f2tf32(fb1.x); u.y = f2tf32(fb1.y); u.z = f2tf32(fb1.z); u.w = f2tf32(fb1.w);
            *(uint4*)&Bs[nb][(bk + 8) * BS_STRIDE + bn] = u;
            __syncthreads();
            buf = nb;
        }
    }

    // epilogue
    float bv[4][2];
    #pragma unroll
    for (int nt = 0; nt < 4; nt++) {
        int c = n0 + wn + (nt << 3) + ((lane & 3) << 1);
        bv[nt][0] = bias[c];
        bv[nt][1] = bias[c + 1];
    }
    #pragma unroll
    for (int mt = 0; mt < 4; mt++) {
        int rr = m0 + wm + (mt << 4) + (lane >> 2);
        int r2 = rr + 8;
        int o1 = SCATTER_C ? rowmap[rr] : rr;
        int o2 = SCATTER_C ? rowmap[r2] : r2;
        #pragma unroll
        for (int nt = 0; nt < 4; nt++) {
            int c = n0 + wn + (nt << 3) + ((lane & 3) << 1);
            float2 v0, v1;
            v0.x = acc[mt][nt][0] + bv[nt][0];
            v0.y = acc[mt][nt][1] + bv[nt][1];
            v1.x = acc[mt][nt][2] + bv[nt][0];
            v1.y = acc[mt][nt][3] + bv[nt][1];
            if (GELU) {
                v0.x = gelu_f(v0.x); v0.y = gelu_f(v0.y);
                v1.x = gelu_f(v1.x); v1.y = gelu_f(v1.y);
            }
            *(float2*)(Cm + (size_t)o1 * N + c) = v0;
            *(float2*)(Cm + (size_t)o2 * N + c) = v1;
        }
    }
}

// ---------------------------------------------------------------------------
// Windowed cosine attention: one block per (window, head). 256 threads.
// ---------------------------------------------------------------------------
__global__ __launch_bounds__(256)
void attn_kernel(const float* __restrict__ qkv, float* __restrict__ out) {
    __shared__ float qs[64][33];
    __shared__ float ks[64][33];
    __shared__ float vs[64][33];
    __shared__ float Ss[64][65];
    __shared__ int lab[64];
    const int t  = threadIdx.x;
    const int b_ = blockIdx.x >> 3, h = blockIdx.x & 7;

    const float* base = qkv + (size_t)b_ * (64 * 768) + h * 32;
    #pragma unroll
    for (int r = 0; r < 8; r++) {
        int idx = r * 256 + t;
        int n = idx >> 5, d = idx & 31;
        const float* p = base + n * 768 + d;
        qs[n][d] = p[0];
        ks[n][d] = p[256];
        vs[n][d] = p[512];
    }
    if (t < 64) {
        int w = b_ & 63;
        int wy = w >> 3, wx = w & 7, ty_ = t >> 3, tx_ = t & 7;
        int gh = wy * 8 + ty_, gw = wx * 8 + tx_;
        int rh = gh < 56 ? 0 : (gh < 60 ? 1 : 2);
        int rw = gw < 56 ? 0 : (gw < 60 ? 1 : 2);
        lab[t] = rh * 3 + rw;
    }
    __syncthreads();

    {
        int row = t >> 2, sl = (t & 3) << 3;
        float s = 0.f;
        #pragma unroll
        for (int dd = 0; dd < 8; dd++) { float v = qs[row][sl + dd]; s += v * v; }
        s += __shfl_xor_sync(0xffffffffu, s, 1);
        s += __shfl_xor_sync(0xffffffffu, s, 2);
        float rn = rsqrtf(fmaxf(s, 1e-12f));
        #pragma unroll
        for (int dd = 0; dd < 8; dd++) qs[row][sl + dd] *= rn;
        s = 0.f;
        #pragma unroll
        for (int dd = 0; dd < 8; dd++) { float v = ks[row][sl + dd]; s += v * v; }
        s += __shfl_xor_sync(0xffffffffu, s, 1);
        s += __shfl_xor_sync(0xffffffffu, s, 2);
        rn = rsqrtf(fmaxf(s, 1e-12f));
        #pragma unroll
        for (int dd = 0; dd < 8; dd++) ks[row][sl + dd] *= rn;
    }
    __syncthreads();

    {
        const int i0 = (t >> 4) << 2, j0 = (t & 15) << 2;
        float accS[4][4];
        #pragma unroll
        for (int a = 0; a < 4; a++)
            #pragma unroll
            for (int b = 0; b < 4; b++) accS[a][b] = 0.f;
        for (int d = 0; d < 32; d++) {
            float qv[4], kv[4];
            #pragma unroll
            for (int c = 0; c < 4; c++) { qv[c] = qs[i0 + c][d]; kv[c] = ks[j0 + c][d]; }
            #pragma unroll
            for (int a = 0; a < 4; a++)
                #pragma unroll
                for (int b = 0; b < 4; b++) accS[a][b] += qv[a] * kv[b];
        }
        const float sc = g_hscale[h];
        const float* rp = g_rpb + h * 4096;
        #pragma unroll
        for (int a = 0; a < 4; a++)
            #pragma unroll
            for (int b = 0; b < 4; b++) {
                int i = i0 + a, j = j0 + b;
                float mval = (lab[i] == lab[j]) ? 0.f : -100.f;
                Ss[i][j] = accS[a][b] * sc + rp[i * 64 + j] + mval;
            }
    }
    __syncthreads();

    {
        int row = t >> 2, sl = (t & 3) << 4;
        float mx = -1e30f;
        float ev[16];
        #pragma unroll
        for (int jj = 0; jj < 16; jj++) mx = fmaxf(mx, Ss[row][sl + jj]);
        mx = fmaxf(mx, __shfl_xor_sync(0xffffffffu, mx, 1));
        mx = fmaxf(mx, __shfl_xor_sync(0xffffffffu, mx, 2));
        float sm = 0.f;
        #pragma unroll
        for (int jj = 0; jj < 16; jj++) { ev[jj] = expf(Ss[row][sl + jj] - mx); sm += ev[jj]; }
        sm += __shfl_xor_sync(0xffffffffu, sm, 1);
        sm += __shfl_xor_sync(0xffffffffu, sm, 2);
        float inv = 1.f / sm;
        #pragma unroll
        for (int jj = 0; jj < 16; jj++) Ss[row][sl + jj] = ev[jj] * inv;
    }
    __syncthreads();

    if (t < 128) {
        const int i0 = (t >> 3) << 2, d0 = (t & 7) << 2;
        float accO[4][4];
        #pragma unroll
        for (int a = 0; a < 4; a++)
            #pragma unroll
            for (int b = 0; b < 4; b++) accO[a][b] = 0.f;
        for (int j = 0; j < 64; j++) {
            float pv[4], vv[4];
            #pragma unroll
            for (int c = 0; c < 4; c++) { pv[c] = Ss[i0 + c][j]; vv[c] = vs[j][d0 + c]; }
            #pragma unroll
            for (int a = 0; a < 4; a++)
                #pragma unroll
                for (int b = 0; b < 4; b++) accO[a][b] += pv[a] * vv[b];
        }
        #pragma unroll
        for (int a = 0; a < 4; a++)
            #pragma unroll
            for (int b = 0; b < 4; b++)
                out[(size_t)(b_ * 64 + i0 + a) * 256 + h * 32 + d0 + b] = accO[a][b];
    }
}

// ---------------------------------------------------------------------------
__global__ __launch_bounds__(256)
void ln_add_kernel(const float* __restrict__ resid, const float* __restrict__ y,
                   const float* __restrict__ sc, const float* __restrict__ bi,
                   float* __restrict__ out) {
    int warp = (blockIdx.x * 256 + threadIdx.x) >> 5;
    int lane = threadIdx.x & 31;
    if (warp >= MROWS) return;
    const float* yr = y + (size_t)warp * 256;
    float v[8];
    #pragma unroll
    for (int i = 0; i < 8; i++) v[i] = yr[lane * 8 + i];
    float s = 0.f;
    #pragma unroll
    for (int i = 0; i < 8; i++) s += v[i];
    #pragma unroll
    for (int o = 16; o > 0; o >>= 1) s += __shfl_xor_sync(0xffffffffu, s, o);
    float mean = s * (1.f / 256.f);
    float sq = 0.f;
    #pragma unroll
    for (int i = 0; i < 8; i++) { float d = v[i] - mean; sq += d * d; }
    #pragma unroll
    for (int o = 16; o > 0; o >>= 1) sq += __shfl_xor_sync(0xffffffffu, sq, o);
    float rstd = rsqrtf(sq * (1.f / 256.f) + 1e-6f);
    const float* rr = resid + (size_t)warp * 256;
    float* op = out + (size_t)warp * 256;
    #pragma unroll
    for (int i = 0; i < 8; i++) {
        int c = lane * 8 + i;
        op[c] = rr[c] + (v[i] - mean) * rstd * sc[c] + bi[c];
    }
}

// ---------------------------------------------------------------------------
extern "C" void kernel_launch(void* const* d_in, const int* in_sizes, int n_in,
                              void* d_out, int out_size) {
    const float* x       = (const float*)d_in[0];
    const float* qkv_w   = (const float*)d_in[1];
    const float* q_bias  = (const float*)d_in[2];
    const float* v_bias  = (const float*)d_in[3];
    const float* lscale  = (const float*)d_in[4];
    const float* cpb_w1  = (const float*)d_in[5];
    const float* cpb_b1  = (const float*)d_in[6];
    const float* cpb_w2  = (const float*)d_in[7];
    const float* proj_w  = (const float*)d_in[8];
    const float* proj_b  = (const float*)d_in[9];
    const float* n1s     = (const float*)d_in[10];
    const float* n1b     = (const float*)d_in[11];
    const float* n2s     = (const float*)d_in[12];
    const float* n2b     = (const float*)d_in[13];
    const float* fc1_w   = (const float*)d_in[14];
    const float* fc1_b   = (const float*)d_in[15];
    const float* fc2_w   = (const float*)d_in[16];
    const float* fc2_b   = (const float*)d_in[17];
    float* out = (float*)d_out;

    void *p_qkv, *p_attn, *p_y, *p_x1, *p_h, *p_h2, *p_qb, *p_rm;
    cudaGetSymbolAddress(&p_qkv,  g_qkv);
    cudaGetSymbolAddress(&p_attn, g_attn);
    cudaGetSymbolAddress(&p_y,    g_y);
    cudaGetSymbolAddress(&p_x1,   g_x1);
    cudaGetSymbolAddress(&p_h,    g_h);
    cudaGetSymbolAddress(&p_h2,   g_h2);
    cudaGetSymbolAddress(&p_qb,   g_qkvbias);
    cudaGetSymbolAddress(&p_rm,   g_rowmap);

    prep_kernel<<<1, 256>>>(lscale, cpb_w1, cpb_b1, cpb_w2, q_bias, v_bias);
    rowmap_kernel<<<512, 256>>>();

    // qkv = gather(x) @ qkv_w + qkv_bias
    gemm_tf32<false, true, false><<<dim3(768 / 128, MROWS / 128), 256>>>(
        x, qkv_w, (const float*)p_qb, (float*)p_qkv, 768, 256, (const int*)p_rm);

    attn_kernel<<<2048 * 8, 256>>>((const float*)p_qkv, (float*)p_attn);

    // y = scatter(attn @ proj_w + proj_b)
    gemm_tf32<false, false, true><<<dim3(256 / 128, MROWS / 128), 256>>>(
        (const float*)p_attn, proj_w, proj_b, (float*)p_y, 256, 256, (const int*)p_rm);

    ln_add_kernel<<<MROWS / 8, 256>>>(x, (const float*)p_y, n1s, n1b, (float*)p_x1);

    // h = gelu(x1 @ fc1_w + fc1_b)
    gemm_tf32<true, false, false><<<dim3(1024 / 128, MROWS / 128), 256>>>(
        (const float*)p_x1, fc1_w, fc1_b, (float*)p_h, 1024, 256, nullptr);

    // h2 = h @ fc2_w + fc2_b
    gemm_tf32<false, false, false><<<dim3(256 / 128, MROWS / 128), 256>>>(
        (const float*)p_h, fc2_w, fc2_b, (float*)p_h2, 256, 1024, nullptr);

    ln_add_kernel<<<MROWS / 8, 256>>>((const float*)p_x1, (const float*)p_h2, n2s, n2b, out);
}

// round 4
// speedup vs baseline: 2.4337x; 1.7611x over previous
#include <cuda_runtime.h>
#include <cuda_fp16.h>
#include <cstdint>

// ---------------------------------------------------------------------------
// SwinV2 block: B=32, H=W=64, C=256, NH=8, HD=32, WS=8, SS=4
// Round 4: fp16 mma.sync.m16n8k16 GEMMs (fp32 accum), fused gather/scatter.
// ---------------------------------------------------------------------------

static constexpr int SSc   = 4;
static constexpr int NTOK  = 64;
static constexpr int NHc   = 8;
static constexpr int Cc    = 256;
static constexpr int MROWS = 131072;
static constexpr int HIDc  = 1024;

__device__ float g_qkv [(size_t)MROWS * 768];
__device__ float g_attn[(size_t)MROWS * Cc];
__device__ float g_y   [(size_t)MROWS * Cc];
__device__ float g_x1  [(size_t)MROWS * Cc];
__device__ float g_h   [(size_t)MROWS * HIDc];
__device__ float g_h2  [(size_t)MROWS * Cc];
__device__ float g_rpb [NHc * NTOK * NTOK];
__device__ float g_qkvbias[768];
__device__ float g_hscale[NHc];
__device__ int   g_rowmap[MROWS];
// fp16 weights, transposed to [N, K] K-major
__device__ __half g_wqkv_h[768 * 256];
__device__ __half g_wproj_h[256 * 256];
__device__ __half g_wfc1_h[1024 * 256];
__device__ __half g_wfc2_h[256 * 1024];

__device__ __forceinline__ float gelu_f(float x) {
    float x3 = x * x * x;
    return 0.5f * x * (1.f + tanhf(0.7978845608028654f * (x + 0.044715f * x3)));
}

__device__ __forceinline__ void mma_f16(float* c, const unsigned* a, const unsigned* b) {
    asm volatile(
        "mma.sync.aligned.m16n8k16.row.col.f32.f16.f16.f32 "
        "{%0,%1,%2,%3}, {%4,%5,%6,%7}, {%8,%9}, {%0,%1,%2,%3};"
        : "+f"(c[0]), "+f"(c[1]), "+f"(c[2]), "+f"(c[3])
        : "r"(a[0]), "r"(a[1]), "r"(a[2]), "r"(a[3]), "r"(b[0]), "r"(b[1]));
}

// ---------------------------------------------------------------------------
__global__ void prep_kernel(const float* __restrict__ logit_scale,
                            const float* __restrict__ cpb_w1,
                            const float* __restrict__ cpb_b1,
                            const float* __restrict__ cpb_w2,
                            const float* __restrict__ q_bias,
                            const float* __restrict__ v_bias) {
    __shared__ float table[225][NHc];
    int t = threadIdx.x;
    for (int i = t; i < 768; i += 256) {
        float v = 0.f;
        if (i < 256)       v = q_bias[i];
        else if (i >= 512) v = v_bias[i - 512];
        g_qkvbias[i] = v;
    }
    if (t < NHc) {
        float ls = logit_scale[t];
        g_hscale[t] = expf(fminf(ls, 4.605170185988092f));
    }
    if (t < 225) {
        int a = t / 15, b = t % 15;
        float f0 = (float)(a - 7) * (8.f / 7.f);
        float f1 = (float)(b - 7) * (8.f / 7.f);
        f0 = copysignf(log2f(fabsf(f0) + 1.f) * (1.f / 3.f), f0);
        f1 = copysignf(log2f(fabsf(f1) + 1.f) * (1.f / 3.f), f1);
        float acc[NHc];
        #pragma unroll
        for (int h = 0; h < NHc; h++) acc[h] = 0.f;
        for (int j = 0; j < 512; j++) {
            float hid = f0 * cpb_w1[j] + f1 * cpb_w1[512 + j] + cpb_b1[j];
            hid = fmaxf(hid, 0.f);
            #pragma unroll
            for (int h = 0; h < NHc; h++) acc[h] += hid * cpb_w2[j * NHc + h];
        }
        #pragma unroll
        for (int h = 0; h < NHc; h++) table[t][h] = acc[h];
    }
    __syncthreads();
    for (int idx = t; idx < NHc * NTOK * NTOK; idx += 256) {
        int h = idx >> 12, rem = idx & 4095, i = rem >> 6, j = rem & 63;
        int iy = i >> 3, ix = i & 7, jy = j >> 3, jx = j & 7;
        int ti = (iy - jy + 7) * 15 + (ix - jx + 7);
        float v = table[ti][h];
        g_rpb[idx] = 16.f / (1.f + expf(-v));
    }
}

__global__ void rowmap_kernel() {
    int r = blockIdx.x * 256 + threadIdx.x;
    if (r >= MROWS) return;
    int b = r >> 12;
    int rem = r & 4095;
    int w = rem >> 6, n = rem & 63;
    int wy = w >> 3, wx = w & 7, ty = n >> 3, tx = n & 7;
    int hs = (wy * 8 + ty + SSc) & 63;
    int ws = (wx * 8 + tx + SSc) & 63;
    g_rowmap[r] = (b << 12) + (hs << 6) + ws;
}

// Wt[n*K + k] = half(W[k*N + n])
__global__ void wtrans_kernel(const float* __restrict__ W, __half* __restrict__ Wt,
                              int K, int N) {
    int idx = blockIdx.x * 256 + threadIdx.x;
    if (idx >= K * N) return;
    int n = idx / K, k = idx - n * K;
    Wt[idx] = __float2half_rn(W[(size_t)k * N + n]);
}

// ---------------------------------------------------------------------------
// fp16 GEMM: C[M,N] = A[M,K] @ W[K,N] + bias (+gelu)
// BM=128, BN=128, BK=16, 256 threads (8 warps 2x4), warp tile 64x32.
// As/Bs: [128 rows][16 halfs], stride 24 halfs (12 words: conflict-free frags).
// A is fp32 (converted at STS); B is pre-converted fp16 [N,K] K-major.
// ---------------------------------------------------------------------------
#define HS_STRIDE 24

template<bool GELU, bool GATHER_A, bool SCATTER_C>
__global__ __launch_bounds__(256)
void gemm_f16(const float* __restrict__ A, const __half* __restrict__ Bt,
              const float* __restrict__ bias, float* __restrict__ Cm,
              int N, int K, const int* __restrict__ rowmap) {
    __shared__ __align__(16) __half As[2][128 * HS_STRIDE];
    __shared__ __align__(16) __half Bs[2][128 * HS_STRIDE];

    const int t = threadIdx.x;
    const int lane = t & 31, wid = t >> 5;
    const int wm = (wid >> 2) << 6;   // 0 or 64
    const int wn = (wid & 3) << 5;    // 0,32,64,96
    const int m0 = blockIdx.y * 128, n0 = blockIdx.x * 128;

    // loader: row am (0..127), halfs ak..ak+7
    const int am = t >> 1;
    const int ak = (t & 1) << 3;
    int ra = m0 + am;
    if (GATHER_A) ra = rowmap[ra];
    const float*  ap = A  + (size_t)ra * K + ak;
    const __half* bp = Bt + (size_t)(n0 + am) * K + ak;

    float acc[4][4][4];
    #pragma unroll
    for (int i = 0; i < 4; i++)
        #pragma unroll
        for (int j = 0; j < 4; j++)
            #pragma unroll
            for (int r = 0; r < 4; r++) acc[i][j][r] = 0.f;

    const int KT = K >> 4;
    float4 fa0 = *(const float4*)ap;
    float4 fa1 = *(const float4*)(ap + 4);
    uint4  ub  = *(const uint4*)bp;

    int buf = 0;
    {
        __half2 h0 = __floats2half2_rn(fa0.x, fa0.y);
        __half2 h1 = __floats2half2_rn(fa0.z, fa0.w);
        __half2 h2 = __floats2half2_rn(fa1.x, fa1.y);
        __half2 h3 = __floats2half2_rn(fa1.z, fa1.w);
        uint4 u;
        u.x = *(unsigned*)&h0; u.y = *(unsigned*)&h1;
        u.z = *(unsigned*)&h2; u.w = *(unsigned*)&h3;
        *(uint4*)&As[0][am * HS_STRIDE + ak] = u;
        *(uint4*)&Bs[0][am * HS_STRIDE + ak] = ub;
    }
    __syncthreads();

    const int qr = lane >> 2;        // 0..7
    const int qk = (lane & 3) << 1;  // 0,2,4,6

    for (int kt = 0; kt < KT; kt++) {
        if (kt + 1 < KT) {
            const float*  app = ap + (kt + 1) * 16;
            const __half* bpp = bp + (kt + 1) * 16;
            fa0 = *(const float4*)app;
            fa1 = *(const float4*)(app + 4);
            ub  = *(const uint4*)bpp;
        }

        const __half* Ab = As[buf];
        const __half* Bb = Bs[buf];
        unsigned afrag[4][4], bfrag[4][2];
        #pragma unroll
        for (int mt = 0; mt < 4; mt++) {
            int r = wm + (mt << 4) + qr;
            afrag[mt][0] = *(const unsigned*)&Ab[r * HS_STRIDE + qk];
            afrag[mt][1] = *(const unsigned*)&Ab[(r + 8) * HS_STRIDE + qk];
            afrag[mt][2] = *(const unsigned*)&Ab[r * HS_STRIDE + qk + 8];
            afrag[mt][3] = *(const unsigned*)&Ab[(r + 8) * HS_STRIDE + qk + 8];
        }
        #pragma unroll
        for (int nt = 0; nt < 4; nt++) {
            int c = wn + (nt << 3) + qr;
            bfrag[nt][0] = *(const unsigned*)&Bb[c * HS_STRIDE + qk];
            bfrag[nt][1] = *(const unsigned*)&Bb[c * HS_STRIDE + qk + 8];
        }
        #pragma unroll
        for (int mt = 0; mt < 4; mt++)
            #pragma unroll
            for (int nt = 0; nt < 4; nt++)
                mma_f16(acc[mt][nt], afrag[mt], bfrag[nt]);

        if (kt + 1 < KT) {
            int nb = buf ^ 1;
            __half2 h0 = __floats2half2_rn(fa0.x, fa0.y);
            __half2 h1 = __floats2half2_rn(fa0.z, fa0.w);
            __half2 h2 = __floats2half2_rn(fa1.x, fa1.y);
            __half2 h3 = __floats2half2_rn(fa1.z, fa1.w);
            uint4 u;
            u.x = *(unsigned*)&h0; u.y = *(unsigned*)&h1;
            u.z = *(unsigned*)&h2; u.w = *(unsigned*)&h3;
            *(uint4*)&As[nb][am * HS_STRIDE + ak] = u;
            *(uint4*)&Bs[nb][am * HS_STRIDE + ak] = ub;
            __syncthreads();
            buf = nb;
        }
    }

    // epilogue
    float bv[4][2];
    #pragma unroll
    for (int nt = 0; nt < 4; nt++) {
        int c = n0 + wn + (nt << 3) + ((lane & 3) << 1);
        bv[nt][0] = bias[c];
        bv[nt][1] = bias[c + 1];
    }
    #pragma unroll
    for (int mt = 0; mt < 4; mt++) {
        int rr = m0 + wm + (mt << 4) + (lane >> 2);
        int r2 = rr + 8;
        int o1 = SCATTER_C ? rowmap[rr] : rr;
        int o2 = SCATTER_C ? rowmap[r2] : r2;
        #pragma unroll
        for (int nt = 0; nt < 4; nt++) {
            int c = n0 + wn + (nt << 3) + ((lane & 3) << 1);
            float2 v0, v1;
            v0.x = acc[mt][nt][0] + bv[nt][0];
            v0.y = acc[mt][nt][1] + bv[nt][1];
            v1.x = acc[mt][nt][2] + bv[nt][0];
            v1.y = acc[mt][nt][3] + bv[nt][1];
            if (GELU) {
                v0.x = gelu_f(v0.x); v0.y = gelu_f(v0.y);
                v1.x = gelu_f(v1.x); v1.y = gelu_f(v1.y);
            }
            *(float2*)(Cm + (size_t)o1 * N + c) = v0;
            *(float2*)(Cm + (size_t)o2 * N + c) = v1;
        }
    }
}

// ---------------------------------------------------------------------------
// Windowed cosine attention: one block per (window, head). 256 threads.
// ---------------------------------------------------------------------------
__global__ __launch_bounds__(256)
void attn_kernel(const float* __restrict__ qkv, float* __restrict__ out) {
    __shared__ float qs[64][33];
    __shared__ float ks[64][33];
    __shared__ float vs[64][33];
    __shared__ float Ss[64][65];
    __shared__ int lab[64];
    const int t  = threadIdx.x;
    const int b_ = blockIdx.x >> 3, h = blockIdx.x & 7;

    const float* base = qkv + (size_t)b_ * (64 * 768) + h * 32;
    #pragma unroll
    for (int r = 0; r < 8; r++) {
        int idx = r * 256 + t;
        int n = idx >> 5, d = idx & 31;
        const float* p = base + n * 768 + d;
        qs[n][d] = p[0];
        ks[n][d] = p[256];
        vs[n][d] = p[512];
    }
    if (t < 64) {
        int w = b_ & 63;
        int wy = w >> 3, wx = w & 7, ty_ = t >> 3, tx_ = t & 7;
        int gh = wy * 8 + ty_, gw = wx * 8 + tx_;
        int rh = gh < 56 ? 0 : (gh < 60 ? 1 : 2);
        int rw = gw < 56 ? 0 : (gw < 60 ? 1 : 2);
        lab[t] = rh * 3 + rw;
    }
    __syncthreads();

    {
        int row = t >> 2, sl = (t & 3) << 3;
        float s = 0.f;
        #pragma unroll
        for (int dd = 0; dd < 8; dd++) { float v = qs[row][sl + dd]; s += v * v; }
        s += __shfl_xor_sync(0xffffffffu, s, 1);
        s += __shfl_xor_sync(0xffffffffu, s, 2);
        float rn = rsqrtf(fmaxf(s, 1e-12f));
        #pragma unroll
        for (int dd = 0; dd < 8; dd++) qs[row][sl + dd] *= rn;
        s = 0.f;
        #pragma unroll
        for (int dd = 0; dd < 8; dd++) { float v = ks[row][sl + dd]; s += v * v; }
        s += __shfl_xor_sync(0xffffffffu, s, 1);
        s += __shfl_xor_sync(0xffffffffu, s, 2);
        rn = rsqrtf(fmaxf(s, 1e-12f));
        #pragma unroll
        for (int dd = 0; dd < 8; dd++) ks[row][sl + dd] *= rn;
    }
    __syncthreads();

    {
        const int i0 = (t >> 4) << 2, j0 = (t & 15) << 2;
        float accS[4][4];
        #pragma unroll
        for (int a = 0; a < 4; a++)
            #pragma unroll
            for (int b = 0; b < 4; b++) accS[a][b] = 0.f;
        for (int d = 0; d < 32; d++) {
            float qv[4], kv[4];
            #pragma unroll
            for (int c = 0; c < 4; c++) { qv[c] = qs[i0 + c][d]; kv[c] = ks[j0 + c][d]; }
            #pragma unroll
            for (int a = 0; a < 4; a++)
                #pragma unroll
                for (int b = 0; b < 4; b++) accS[a][b] += qv[a] * kv[b];
        }
        const float sc = g_hscale[h];
        const float* rp = g_rpb + h * 4096;
        #pragma unroll
        for (int a = 0; a < 4; a++)
            #pragma unroll
            for (int b = 0; b < 4; b++) {
                int i = i0 + a, j = j0 + b;
                float mval = (lab[i] == lab[j]) ? 0.f : -100.f;
                Ss[i][j] = accS[a][b] * sc + rp[i * 64 + j] + mval;
            }
    }
    __syncthreads();

    {
        int row = t >> 2, sl = (t & 3) << 4;
        float mx = -1e30f;
        float ev[16];
        #pragma unroll
        for (int jj = 0; jj < 16; jj++) mx = fmaxf(mx, Ss[row][sl + jj]);
        mx = fmaxf(mx, __shfl_xor_sync(0xffffffffu, mx, 1));
        mx = fmaxf(mx, __shfl_xor_sync(0xffffffffu, mx, 2));
        float sm = 0.f;
        #pragma unroll
        for (int jj = 0; jj < 16; jj++) { ev[jj] = expf(Ss[row][sl + jj] - mx); sm += ev[jj]; }
        sm += __shfl_xor_sync(0xffffffffu, sm, 1);
        sm += __shfl_xor_sync(0xffffffffu, sm, 2);
        float inv = 1.f / sm;
        #pragma unroll
        for (int jj = 0; jj < 16; jj++) Ss[row][sl + jj] = ev[jj] * inv;
    }
    __syncthreads();

    if (t < 128) {
        const int i0 = (t >> 3) << 2, d0 = (t & 7) << 2;
        float accO[4][4];
        #pragma unroll
        for (int a = 0; a < 4; a++)
            #pragma unroll
            for (int b = 0; b < 4; b++) accO[a][b] = 0.f;
        for (int j = 0; j < 64; j++) {
            float pv[4], vv[4];
            #pragma unroll
            for (int c = 0; c < 4; c++) { pv[c] = Ss[i0 + c][j]; vv[c] = vs[j][d0 + c]; }
            #pragma unroll
            for (int a = 0; a < 4; a++)
                #pragma unroll
                for (int b = 0; b < 4; b++) accO[a][b] += pv[a] * vv[b];
        }
        #pragma unroll
        for (int a = 0; a < 4; a++)
            #pragma unroll
            for (int b = 0; b < 4; b++)
                out[(size_t)(b_ * 64 + i0 + a) * 256 + h * 32 + d0 + b] = accO[a][b];
    }
}

// ---------------------------------------------------------------------------
__global__ __launch_bounds__(256)
void ln_add_kernel(const float* __restrict__ resid, const float* __restrict__ y,
                   const float* __restrict__ sc, const float* __restrict__ bi,
                   float* __restrict__ out) {
    int warp = (blockIdx.x * 256 + threadIdx.x) >> 5;
    int lane = threadIdx.x & 31;
    if (warp >= MROWS) return;
    const float* yr = y + (size_t)warp * 256;
    float v[8];
    #pragma unroll
    for (int i = 0; i < 8; i++) v[i] = yr[lane * 8 + i];
    float s = 0.f;
    #pragma unroll
    for (int i = 0; i < 8; i++) s += v[i];
    #pragma unroll
    for (int o = 16; o > 0; o >>= 1) s += __shfl_xor_sync(0xffffffffu, s, o);
    float mean = s * (1.f / 256.f);
    float sq = 0.f;
    #pragma unroll
    for (int i = 0; i < 8; i++) { float d = v[i] - mean; sq += d * d; }
    #pragma unroll
    for (int o = 16; o > 0; o >>= 1) sq += __shfl_xor_sync(0xffffffffu, sq, o);
    float rstd = rsqrtf(sq * (1.f / 256.f) + 1e-6f);
    const float* rr = resid + (size_t)warp * 256;
    float* op = out + (size_t)warp * 256;
    #pragma unroll
    for (int i = 0; i < 8; i++) {
        int c = lane * 8 + i;
        op[c] = rr[c] + (v[i] - mean) * rstd * sc[c] + bi[c];
    }
}

// ---------------------------------------------------------------------------
extern "C" void kernel_launch(void* const* d_in, const int* in_sizes, int n_in,
                              void* d_out, int out_size) {
    const float* x       = (const float*)d_in[0];
    const float* qkv_w   = (const float*)d_in[1];
    const float* q_bias  = (const float*)d_in[2];
    const float* v_bias  = (const float*)d_in[3];
    const float* lscale  = (const float*)d_in[4];
    const float* cpb_w1  = (const float*)d_in[5];
    const float* cpb_b1  = (const float*)d_in[6];
    const float* cpb_w2  = (const float*)d_in[7];
    const float* proj_w  = (const float*)d_in[8];
    const float* proj_b  = (const float*)d_in[9];
    const float* n1s     = (const float*)d_in[10];
    const float* n1b     = (const float*)d_in[11];
    const float* n2s     = (const float*)d_in[12];
    const float* n2b     = (const float*)d_in[13];
    const float* fc1_w   = (const float*)d_in[14];
    const float* fc1_b   = (const float*)d_in[15];
    const float* fc2_w   = (const float*)d_in[16];
    const float* fc2_b   = (const float*)d_in[17];
    float* out = (float*)d_out;

    void *p_qkv, *p_attn, *p_y, *p_x1, *p_h, *p_h2, *p_qb, *p_rm;
    void *p_wqkv, *p_wproj, *p_wfc1, *p_wfc2;
    cudaGetSymbolAddress(&p_qkv,  g_qkv);
    cudaGetSymbolAddress(&p_attn, g_attn);
    cudaGetSymbolAddress(&p_y,    g_y);
    cudaGetSymbolAddress(&p_x1,   g_x1);
    cudaGetSymbolAddress(&p_h,    g_h);
    cudaGetSymbolAddress(&p_h2,   g_h2);
    cudaGetSymbolAddress(&p_qb,   g_qkvbias);
    cudaGetSymbolAddress(&p_rm,   g_rowmap);
    cudaGetSymbolAddress(&p_wqkv,  g_wqkv_h);
    cudaGetSymbolAddress(&p_wproj, g_wproj_h);
    cudaGetSymbolAddress(&p_wfc1,  g_wfc1_h);
    cudaGetSymbolAddress(&p_wfc2,  g_wfc2_h);

    prep_kernel<<<1, 256>>>(lscale, cpb_w1, cpb_b1, cpb_w2, q_bias, v_bias);
    rowmap_kernel<<<512, 256>>>();
    wtrans_kernel<<<768,  256>>>(qkv_w,  (__half*)p_wqkv,  256, 768);
    wtrans_kernel<<<256,  256>>>(proj_w, (__half*)p_wproj, 256, 256);
    wtrans_kernel<<<1024, 256>>>(fc1_w,  (__half*)p_wfc1,  256, 1024);
    wtrans_kernel<<<1024, 256>>>(fc2_w,  (__half*)p_wfc2,  1024, 256);

    // qkv = gather(x) @ qkv_w + qkv_bias
    gemm_f16<false, true, false><<<dim3(768 / 128, MROWS / 128), 256>>>(
        x, (const __half*)p_wqkv, (const float*)p_qb, (float*)p_qkv,
        768, 256, (const int*)p_rm);

    attn_kernel<<<2048 * 8, 256>>>((const float*)p_qkv, (float*)p_attn);

    // y = scatter(attn @ proj_w + proj_b)
    gemm_f16<false, false, true><<<dim3(256 / 128, MROWS / 128), 256>>>(
        (const float*)p_attn, (const __half*)p_wproj, proj_b, (float*)p_y,
        256, 256, (const int*)p_rm);

    ln_add_kernel<<<MROWS / 8, 256>>>(x, (const float*)p_y, n1s, n1b, (float*)p_x1);

    // h = gelu(x1 @ fc1_w + fc1_b)
    gemm_f16<true, false, false><<<dim3(1024 / 128, MROWS / 128), 256>>>(
        (const float*)p_x1, (const __half*)p_wfc1, fc1_b, (float*)p_h,
        1024, 256, nullptr);

    // h2 = h @ fc2_w + fc2_b
    gemm_f16<false, false, false><<<dim3(256 / 128, MROWS / 128), 256>>>(
        (const float*)p_h, (const __half*)p_wfc2, fc2_b, (float*)p_h2,
        256, 1024, nullptr);

    ln_add_kernel<<<MROWS / 8, 256>>>((const float*)p_x1, (const float*)p_h2, n2s, n2b, out);
}

// round 10
// speedup vs baseline: 2.6614x; 1.0936x over previous
#include <cuda_runtime.h>
#include <cuda_fp16.h>
#include <cstdint>

// ---------------------------------------------------------------------------
// SwinV2 block: B=32, H=W=64, C=256, NH=8, HD=32, WS=8, SS=4
// Round 7 (= round-5 kernel, resubmitted after infra failure):
// fp16 mma + ldmatrix fragments + fp16 A-side intermediates.
// ---------------------------------------------------------------------------

static constexpr int SSc   = 4;
static constexpr int NTOK  = 64;
static constexpr int NHc   = 8;
static constexpr int Cc    = 256;
static constexpr int MROWS = 131072;
static constexpr int HIDc  = 1024;

__device__ float  g_qkv [(size_t)MROWS * 768];     // fp32: attention needs it
__device__ __half g_attn[(size_t)MROWS * Cc];      // fp16: proj A input
__device__ float  g_y   [(size_t)MROWS * Cc];
__device__ float  g_x1  [(size_t)MROWS * Cc];      // fp32: residual
__device__ __half g_x1h [(size_t)MROWS * Cc];      // fp16 mirror: fc1 A input
__device__ __half g_h   [(size_t)MROWS * HIDc];    // fp16: fc2 A input
__device__ float  g_h2  [(size_t)MROWS * Cc];
__device__ __half g_xh  [(size_t)MROWS * Cc];      // fp16 gathered x: qkv A input
__device__ float  g_rpb [NHc * NTOK * NTOK];
__device__ float  g_qkvbias[768];
__device__ float  g_hscale[NHc];
__device__ int    g_rowmap[MROWS];
// fp16 weights, transposed to [N, K] K-major
__device__ __half g_wqkv_h[768 * 256];
__device__ __half g_wproj_h[256 * 256];
__device__ __half g_wfc1_h[1024 * 256];
__device__ __half g_wfc2_h[256 * 1024];

__device__ __forceinline__ float gelu_f(float x) {
    float x3 = x * x * x;
    return 0.5f * x * (1.f + tanhf(0.7978845608028654f * (x + 0.044715f * x3)));
}
__device__ __forceinline__ uint32_t smem_u32(const void* p) {
    uint32_t a;
    asm("{ .reg .u64 t; cvta.to.shared.u64 t, %1; cvt.u32.u64 %0, t; }" : "=r"(a) : "l"(p));
    return a;
}
__device__ __forceinline__ void mma_f16(float* c, const unsigned* a, const unsigned* b) {
    asm volatile(
        "mma.sync.aligned.m16n8k16.row.col.f32.f16.f16.f32 "
        "{%0,%1,%2,%3}, {%4,%5,%6,%7}, {%8,%9}, {%0,%1,%2,%3};"
        : "+f"(c[0]), "+f"(c[1]), "+f"(c[2]), "+f"(c[3])
        : "r"(a[0]), "r"(a[1]), "r"(a[2]), "r"(a[3]), "r"(b[0]), "r"(b[1]));
}
__device__ __forceinline__ void ldsm4(unsigned* r, uint32_t addr) {
    asm volatile("ldmatrix.sync.aligned.m8n8.x4.shared.b16 {%0,%1,%2,%3}, [%4];"
        : "=r"(r[0]), "=r"(r[1]), "=r"(r[2]), "=r"(r[3]) : "r"(addr));
}

// ---------------------------------------------------------------------------
__global__ void prep_kernel(const float* __restrict__ logit_scale,
                            const float* __restrict__ cpb_w1,
                            const float* __restrict__ cpb_b1,
                            const float* __restrict__ cpb_w2,
                            const float* __restrict__ q_bias,
                            const float* __restrict__ v_bias) {
    __shared__ float table[225][NHc];
    int t = threadIdx.x;
    for (int i = t; i < 768; i += 256) {
        float v = 0.f;
        if (i < 256)       v = q_bias[i];
        else if (i >= 512) v = v_bias[i - 512];
        g_qkvbias[i] = v;
    }
    if (t < NHc) {
        float ls = logit_scale[t];
        g_hscale[t] = expf(fminf(ls, 4.605170185988092f));
    }
    if (t < 225) {
        int a = t / 15, b = t % 15;
        float f0 = (float)(a - 7) * (8.f / 7.f);
        float f1 = (float)(b - 7) * (8.f / 7.f);
        f0 = copysignf(log2f(fabsf(f0) + 1.f) * (1.f / 3.f), f0);
        f1 = copysignf(log2f(fabsf(f1) + 1.f) * (1.f / 3.f), f1);
        float acc[NHc];
        #pragma unroll
        for (int h = 0; h < NHc; h++) acc[h] = 0.f;
        for (int j = 0; j < 512; j++) {
            float hid = f0 * cpb_w1[j] + f1 * cpb_w1[512 + j] + cpb_b1[j];
            hid = fmaxf(hid, 0.f);
            #pragma unroll
            for (int h = 0; h < NHc; h++) acc[h] += hid * cpb_w2[j * NHc + h];
        }
        #pragma unroll
        for (int h = 0; h < NHc; h++) table[t][h] = acc[h];
    }
    __syncthreads();
    for (int idx = t; idx < NHc * NTOK * NTOK; idx += 256) {
        int h = idx >> 12, rem = idx & 4095, i = rem >> 6, j = rem & 63;
        int iy = i >> 3, ix = i & 7, jy = j >> 3, jx = j & 7;
        int ti = (iy - jy + 7) * 15 + (ix - jx + 7);
        float v = table[ti][h];
        g_rpb[idx] = 16.f / (1.f + expf(-v));
    }
}

__global__ void rowmap_kernel() {
    int r = blockIdx.x * 256 + threadIdx.x;
    if (r >= MROWS) return;
    int b = r >> 12;
    int rem = r & 4095;
    int w = rem >> 6, n = rem & 63;
    int wy = w >> 3, wx = w & 7, ty = n >> 3, tx = n & 7;
    int hs = (wy * 8 + ty + SSc) & 63;
    int ws = (wx * 8 + tx + SSc) & 63;
    g_rowmap[r] = (b << 12) + (hs << 6) + ws;
}

// gathered fp16 copy of x: g_xh[r] = half(x[map(r)])
__global__ void xgather_kernel(const float* __restrict__ x) {
    int idx = blockIdx.x * 256 + threadIdx.x;        // 8 floats per thread
    int base = idx << 3;
    int row = base >> 8, col = base & 255;
    int b = row >> 12, rem = row & 4095;
    int w = rem >> 6, n = rem & 63;
    int wy = w >> 3, wx = w & 7, ty = n >> 3, tx = n & 7;
    int hs = (wy * 8 + ty + SSc) & 63;
    int ws = (wx * 8 + tx + SSc) & 63;
    int src = (b << 12) + (hs << 6) + ws;
    const float* p = x + (size_t)src * 256 + col;
    float4 f0 = *(const float4*)p;
    float4 f1 = *(const float4*)(p + 4);
    __half2 h0 = __floats2half2_rn(f0.x, f0.y);
    __half2 h1 = __floats2half2_rn(f0.z, f0.w);
    __half2 h2 = __floats2half2_rn(f1.x, f1.y);
    __half2 h3 = __floats2half2_rn(f1.z, f1.w);
    uint4 u;
    u.x = *(unsigned*)&h0; u.y = *(unsigned*)&h1;
    u.z = *(unsigned*)&h2; u.w = *(unsigned*)&h3;
    *(uint4*)(g_xh + (size_t)row * 256 + col) = u;
}

// Wt[n*K + k] = half(W[k*N + n])
__global__ void wtrans_kernel(const float* __restrict__ W, __half* __restrict__ Wt,
                              int K, int N) {
    int idx = blockIdx.x * 256 + threadIdx.x;
    if (idx >= K * N) return;
    int n = idx / K, k = idx - n * K;
    Wt[idx] = __float2half_rn(W[(size_t)k * N + n]);
}

// ---------------------------------------------------------------------------
// fp16 GEMM: C[M,N] = A[M,K] @ W[K,N] + bias (+gelu)
// A fp16 [M,K]; B fp16 [N,K] K-major. BM=BN=128, BK=16, 8 warps (2x4),
// warp tile 64x32. smem stride 24 halfs; ldmatrix.x4 fragment loads.
// ---------------------------------------------------------------------------
#define HS_STRIDE 24

template<bool GELU, bool SCATTER_C, bool OUT_HALF>
__global__ __launch_bounds__(256)
void gemm_f16(const __half* __restrict__ A, const __half* __restrict__ Bt,
              const float* __restrict__ bias, void* __restrict__ Cm,
              int N, int K, const int* __restrict__ rowmap) {
    __shared__ __align__(16) __half As[2][128 * HS_STRIDE];
    __shared__ __align__(16) __half Bs[2][128 * HS_STRIDE];

    const int t = threadIdx.x;
    const int lane = t & 31, wid = t >> 5;
    const int wm = (wid >> 2) << 6;   // 0 or 64
    const int wn = (wid & 3) << 5;    // 0,32,64,96
    const int m0 = blockIdx.y * 128, n0 = blockIdx.x * 128;

    // loader: row am (0..127), 8 halfs at ak
    const int am = t >> 1;
    const int ak = (t & 1) << 3;
    const __half* ap = A  + (size_t)(m0 + am) * K + ak;
    const __half* bp = Bt + (size_t)(n0 + am) * K + ak;

    // ldmatrix source addresses
    const int quad = lane >> 3, lr = lane & 7;
    const uint32_t a_addr0 = smem_u32(&As[0][(wm + ((quad & 1) << 3) + lr) * HS_STRIDE
                                             + ((quad >> 1) << 3)]);
    const uint32_t b_addr0 = smem_u32(&Bs[0][(wn + ((quad >> 1) << 3) + lr) * HS_STRIDE
                                             + ((quad & 1) << 3)]);
    const uint32_t BUFB = 128 * HS_STRIDE * 2;   // bytes per buffer
    const uint32_t MTB  = 16 * HS_STRIDE * 2;    // bytes per 16 rows

    float acc[4][4][4];
    #pragma unroll
    for (int i = 0; i < 4; i++)
        #pragma unroll
        for (int j = 0; j < 4; j++)
            #pragma unroll
            for (int r = 0; r < 4; r++) acc[i][j][r] = 0.f;

    const int KT = K >> 4;
    uint4 ua = *(const uint4*)ap;
    uint4 ub = *(const uint4*)bp;
    int buf = 0;
    *(uint4*)&As[0][am * HS_STRIDE + ak] = ua;
    *(uint4*)&Bs[0][am * HS_STRIDE + ak] = ub;
    __syncthreads();

    for (int kt = 0; kt < KT; kt++) {
        if (kt + 1 < KT) {
            ua = *(const uint4*)(ap + (kt + 1) * 16);
            ub = *(const uint4*)(bp + (kt + 1) * 16);
        }

        unsigned afrag[4][4], bfrag[4][2];
        {
            const uint32_t ab = a_addr0 + buf * BUFB;
            #pragma unroll
            for (int mt = 0; mt < 4; mt++) ldsm4(afrag[mt], ab + mt * MTB);
            const uint32_t bb = b_addr0 + buf * BUFB;
            unsigned tmp[4];
            ldsm4(tmp, bb);
            bfrag[0][0] = tmp[0]; bfrag[0][1] = tmp[1];
            bfrag[1][0] = tmp[2]; bfrag[1][1] = tmp[3];
            ldsm4(tmp, bb + MTB);
            bfrag[2][0] = tmp[0]; bfrag[2][1] = tmp[1];
            bfrag[3][0] = tmp[2]; bfrag[3][1] = tmp[3];
        }
        #pragma unroll
        for (int mt = 0; mt < 4; mt++)
            #pragma unroll
            for (int nt = 0; nt < 4; nt++)
                mma_f16(acc[mt][nt], afrag[mt], bfrag[nt]);

        if (kt + 1 < KT) {
            int nb = buf ^ 1;
            *(uint4*)&As[nb][am * HS_STRIDE + ak] = ua;
            *(uint4*)&Bs[nb][am * HS_STRIDE + ak] = ub;
            __syncthreads();
            buf = nb;
        }
    }

    // epilogue
    float bv[4][2];
    #pragma unroll
    for (int nt = 0; nt < 4; nt++) {
        int c = n0 + wn + (nt << 3) + ((lane & 3) << 1);
        bv[nt][0] = bias[c];
        bv[nt][1] = bias[c + 1];
    }
    #pragma unroll
    for (int mt = 0; mt < 4; mt++) {
        int rr = m0 + wm + (mt << 4) + (lane >> 2);
        int r2 = rr + 8;
        int o1 = SCATTER_C ? rowmap[rr] : rr;
        int o2 = SCATTER_C ? rowmap[r2] : r2;
        #pragma unroll
        for (int nt = 0; nt < 4; nt++) {
            int c = n0 + wn + (nt << 3) + ((lane & 3) << 1);
            float2 v0, v1;
            v0.x = acc[mt][nt][0] + bv[nt][0];
            v0.y = acc[mt][nt][1] + bv[nt][1];
            v1.x = acc[mt][nt][2] + bv[nt][0];
            v1.y = acc[mt][nt][3] + bv[nt][1];
            if (GELU) {
                v0.x = gelu_f(v0.x); v0.y = gelu_f(v0.y);
                v1.x = gelu_f(v1.x); v1.y = gelu_f(v1.y);
            }
            if (OUT_HALF) {
                __half* C = (__half*)Cm;
                *(__half2*)(C + (size_t)o1 * N + c) = __floats2half2_rn(v0.x, v0.y);
                *(__half2*)(C + (size_t)o2 * N + c) = __floats2half2_rn(v1.x, v1.y);
            } else {
                float* C = (float*)Cm;
                *(float2*)(C + (size_t)o1 * N + c) = v0;
                *(float2*)(C + (size_t)o2 * N + c) = v1;
            }
        }
    }
}

// ---------------------------------------------------------------------------
// Windowed cosine attention: one block per (window, head). 256 threads.
// Reads fp32 qkv; writes fp16 attn output.
// ---------------------------------------------------------------------------
__global__ __launch_bounds__(256)
void attn_kernel(const float* __restrict__ qkv, __half* __restrict__ out) {
    __shared__ float qs[64][33];
    __shared__ float ks[64][33];
    __shared__ float vs[64][33];
    __shared__ float Ss[64][65];
    __shared__ int lab[64];
    const int t  = threadIdx.x;
    const int b_ = blockIdx.x >> 3, h = blockIdx.x & 7;

    const float* base = qkv + (size_t)b_ * (64 * 768) + h * 32;
    #pragma unroll
    for (int r = 0; r < 2; r++) {
        int idx = r * 256 + t;              // 512 quads of 4
        int n = idx >> 3, d4 = (idx & 7) << 2;
        const float* p = base + n * 768 + d4;
        float4 q4 = *(const float4*)p;
        float4 k4 = *(const float4*)(p + 256);
        float4 v4 = *(const float4*)(p + 512);
        qs[n][d4] = q4.x; qs[n][d4 + 1] = q4.y; qs[n][d4 + 2] = q4.z; qs[n][d4 + 3] = q4.w;
        ks[n][d4] = k4.x; ks[n][d4 + 1] = k4.y; ks[n][d4 + 2] = k4.z; ks[n][d4 + 3] = k4.w;
        vs[n][d4] = v4.x; vs[n][d4 + 1] = v4.y; vs[n][d4 + 2] = v4.z; vs[n][d4 + 3] = v4.w;
    }
    if (t < 64) {
        int w = b_ & 63;
        int wy = w >> 3, wx = w & 7, ty_ = t >> 3, tx_ = t & 7;
        int gh = wy * 8 + ty_, gw = wx * 8 + tx_;
        int rh = gh < 56 ? 0 : (gh < 60 ? 1 : 2);
        int rw = gw < 56 ? 0 : (gw < 60 ? 1 : 2);
        lab[t] = rh * 3 + rw;
    }
    __syncthreads();

    {
        int row = t >> 2, sl = (t & 3) << 3;
        float s = 0.f;
        #pragma unroll
        for (int dd = 0; dd < 8; dd++) { float v = qs[row][sl + dd]; s += v * v; }
        s += __shfl_xor_sync(0xffffffffu, s, 1);
        s += __shfl_xor_sync(0xffffffffu, s, 2);
        float rn = rsqrtf(fmaxf(s, 1e-12f));
        #pragma unroll
        for (int dd = 0; dd < 8; dd++) qs[row][sl + dd] *= rn;
        s = 0.f;
        #pragma unroll
        for (int dd = 0; dd < 8; dd++) { float v = ks[row][sl + dd]; s += v * v; }
        s += __shfl_xor_sync(0xffffffffu, s, 1);
        s += __shfl_xor_sync(0xffffffffu, s, 2);
        rn = rsqrtf(fmaxf(s, 1e-12f));
        #pragma unroll
        for (int dd = 0; dd < 8; dd++) ks[row][sl + dd] *= rn;
    }
    __syncthreads();

    {
        const int i0 = (t >> 4) << 2, j0 = (t & 15) << 2;
        float accS[4][4];
        #pragma unroll
        for (int a = 0; a < 4; a++)
            #pragma unroll
            for (int b = 0; b < 4; b++) accS[a][b] = 0.f;
        for (int d = 0; d < 32; d++) {
            float qv[4], kv[4];
            #pragma unroll
            for (int c = 0; c < 4; c++) { qv[c] = qs[i0 + c][d]; kv[c] = ks[j0 + c][d]; }
            #pragma unroll
            for (int a = 0; a < 4; a++)
                #pragma unroll
                for (int b = 0; b < 4; b++) accS[a][b] += qv[a] * kv[b];
        }
        const float sc = g_hscale[h];
        const float* rp = g_rpb + h * 4096;
        #pragma unroll
        for (int a = 0; a < 4; a++)
            #pragma unroll
            for (int b = 0; b < 4; b++) {
                int i = i0 + a, j = j0 + b;
                float mval = (lab[i] == lab[j]) ? 0.f : -100.f;
                Ss[i][j] = accS[a][b] * sc + rp[i * 64 + j] + mval;
            }
    }
    __syncthreads();

    {
        int row = t >> 2, sl = (t & 3) << 4;
        float mx = -1e30f;
        float ev[16];
        #pragma unroll
        for (int jj = 0; jj < 16; jj++) mx = fmaxf(mx, Ss[row][sl + jj]);
        mx = fmaxf(mx, __shfl_xor_sync(0xffffffffu, mx, 1));
        mx = fmaxf(mx, __shfl_xor_sync(0xffffffffu, mx, 2));
        float sm = 0.f;
        #pragma unroll
        for (int jj = 0; jj < 16; jj++) { ev[jj] = expf(Ss[row][sl + jj] - mx); sm += ev[jj]; }
        sm += __shfl_xor_sync(0xffffffffu, sm, 1);
        sm += __shfl_xor_sync(0xffffffffu, sm, 2);
        float inv = 1.f / sm;
        #pragma unroll
        for (int jj = 0; jj < 16; jj++) Ss[row][sl + jj] = ev[jj] * inv;
    }
    __syncthreads();

    // O = P @ V : 256 threads, 2x4 tile each
    {
        const int i0 = (t >> 3) << 1, d0 = (t & 7) << 2;
        float accO[2][4];
        #pragma unroll
        for (int a = 0; a < 2; a++)
            #pragma unroll
            for (int b = 0; b < 4; b++) accO[a][b] = 0.f;
        for (int j = 0; j < 64; j++) {
            float pv0 = Ss[i0][j], pv1 = Ss[i0 + 1][j];
            float vv[4];
            #pragma unroll
            for (int c = 0; c < 4; c++) vv[c] = vs[j][d0 + c];
            #pragma unroll
            for (int b = 0; b < 4; b++) {
                accO[0][b] += pv0 * vv[b];
                accO[1][b] += pv1 * vv[b];
            }
        }
        #pragma unroll
        for (int a = 0; a < 2; a++) {
            __half* op = out + (size_t)(b_ * 64 + i0 + a) * 256 + h * 32 + d0;
            *(__half2*)op       = __floats2half2_rn(accO[a][0], accO[a][1]);
            *(__half2*)(op + 2) = __floats2half2_rn(accO[a][2], accO[a][3]);
        }
    }
}

// ---------------------------------------------------------------------------
// out = resid + LayerNorm(y)*sc + bi ; optional fp16 mirror
// ---------------------------------------------------------------------------
template<bool WRITE_H>
__global__ __launch_bounds__(256)
void ln_add_kernel(const float* __restrict__ resid, const float* __restrict__ y,
                   const float* __restrict__ sc, const float* __restrict__ bi,
                   float* __restrict__ out, __half* __restrict__ outh) {
    int warp = (blockIdx.x * 256 + threadIdx.x) >> 5;
    int lane = threadIdx.x & 31;
    if (warp >= MROWS) return;
    const float* yr = y + (size_t)warp * 256;
    float v[8];
    #pragma unroll
    for (int i = 0; i < 8; i++) v[i] = yr[lane * 8 + i];
    float s = 0.f;
    #pragma unroll
    for (int i = 0; i < 8; i++) s += v[i];
    #pragma unroll
    for (int o = 16; o > 0; o >>= 1) s += __shfl_xor_sync(0xffffffffu, s, o);
    float mean = s * (1.f / 256.f);
    float sq = 0.f;
    #pragma unroll
    for (int i = 0; i < 8; i++) { float d = v[i] - mean; sq += d * d; }
    #pragma unroll
    for (int o = 16; o > 0; o >>= 1) sq += __shfl_xor_sync(0xffffffffu, sq, o);
    float rstd = rsqrtf(sq * (1.f / 256.f) + 1e-6f);
    const float* rr = resid + (size_t)warp * 256;
    float* op = out + (size_t)warp * 256;
    float ov[8];
    #pragma unroll
    for (int i = 0; i < 8; i++) {
        int c = lane * 8 + i;
        ov[i] = rr[c] + (v[i] - mean) * rstd * sc[c] + bi[c];
        op[c] = ov[i];
    }
    if (WRITE_H) {
        __half2 h0 = __floats2half2_rn(ov[0], ov[1]);
        __half2 h1 = __floats2half2_rn(ov[2], ov[3]);
        __half2 h2 = __floats2half2_rn(ov[4], ov[5]);
        __half2 h3 = __floats2half2_rn(ov[6], ov[7]);
        uint4 u;
        u.x = *(unsigned*)&h0; u.y = *(unsigned*)&h1;
        u.z = *(unsigned*)&h2; u.w = *(unsigned*)&h3;
        *(uint4*)(outh + (size_t)warp * 256 + lane * 8) = u;
    }
}

// ---------------------------------------------------------------------------
extern "C" void kernel_launch(void* const* d_in, const int* in_sizes, int n_in,
                              void* d_out, int out_size) {
    const float* x       = (const float*)d_in[0];
    const float* qkv_w   = (const float*)d_in[1];
    const float* q_bias  = (const float*)d_in[2];
    const float* v_bias  = (const float*)d_in[3];
    const float* lscale  = (const float*)d_in[4];
    const float* cpb_w1  = (const float*)d_in[5];
    const float* cpb_b1  = (const float*)d_in[6];
    const float* cpb_w2  = (const float*)d_in[7];
    const float* proj_w  = (const float*)d_in[8];
    const float* proj_b  = (const float*)d_in[9];
    const float* n1s     = (const float*)d_in[10];
    const float* n1b     = (const float*)d_in[11];
    const float* n2s     = (const float*)d_in[12];
    const float* n2b     = (const float*)d_in[13];
    const float* fc1_w   = (const float*)d_in[14];
    const float* fc1_b   = (const float*)d_in[15];
    const float* fc2_w   = (const float*)d_in[16];
    const float* fc2_b   = (const float*)d_in[17];
    float* out = (float*)d_out;

    void *p_qkv, *p_attn, *p_y, *p_x1, *p_x1h, *p_h, *p_h2, *p_xh, *p_qb, *p_rm;
    void *p_wqkv, *p_wproj, *p_wfc1, *p_wfc2;
    cudaGetSymbolAddress(&p_qkv,  g_qkv);
    cudaGetSymbolAddress(&p_attn, g_attn);
    cudaGetSymbolAddress(&p_y,    g_y);
    cudaGetSymbolAddress(&p_x1,   g_x1);
    cudaGetSymbolAddress(&p_x1h,  g_x1h);
    cudaGetSymbolAddress(&p_h,    g_h);
    cudaGetSymbolAddress(&p_h2,   g_h2);
    cudaGetSymbolAddress(&p_xh,   g_xh);
    cudaGetSymbolAddress(&p_qb,   g_qkvbias);
    cudaGetSymbolAddress(&p_rm,   g_rowmap);
    cudaGetSymbolAddress(&p_wqkv,  g_wqkv_h);
    cudaGetSymbolAddress(&p_wproj, g_wproj_h);
    cudaGetSymbolAddress(&p_wfc1,  g_wfc1_h);
    cudaGetSymbolAddress(&p_wfc2,  g_wfc2_h);

    prep_kernel<<<1, 256>>>(lscale, cpb_w1, cpb_b1, cpb_w2, q_bias, v_bias);
    rowmap_kernel<<<512, 256>>>();
    xgather_kernel<<<16384, 256>>>(x);
    wtrans_kernel<<<768,  256>>>(qkv_w,  (__half*)p_wqkv,  256, 768);
    wtrans_kernel<<<256,  256>>>(proj_w, (__half*)p_wproj, 256, 256);
    wtrans_kernel<<<1024, 256>>>(fc1_w,  (__half*)p_wfc1,  256, 1024);
    wtrans_kernel<<<1024, 256>>>(fc2_w,  (__half*)p_wfc2,  1024, 256);

    // qkv = xh @ qkv_w + qkv_bias   (A already gathered)
    gemm_f16<false, false, false><<<dim3(6, 1024), 256>>>(
        (const __half*)p_xh, (const __half*)p_wqkv, (const float*)p_qb,
        p_qkv, 768, 256, nullptr);

    attn_kernel<<<2048 * 8, 256>>>((const float*)p_qkv, (__half*)p_attn);

    // y = scatter(attn @ proj_w + proj_b)
    gemm_f16<false, true, false><<<dim3(2, 1024), 256>>>(
        (const __half*)p_attn, (const __half*)p_wproj, proj_b,
        p_y, 256, 256, (const int*)p_rm);

    // x1 = x + LN(y)  (fp32 + fp16 mirror)
    ln_add_kernel<true><<<MROWS / 8, 256>>>(x, (const float*)p_y, n1s, n1b,
                                            (float*)p_x1, (__half*)p_x1h);

    // h = gelu(x1 @ fc1_w + fc1_b)  -> fp16
    gemm_f16<true, false, true><<<dim3(8, 1024), 256>>>(
        (const __half*)p_x1h, (const __half*)p_wfc1, fc1_b,
        p_h, 1024, 256, nullptr);

    // h2 = h @ fc2_w + fc2_b
    gemm_f16<false, false, false><<<dim3(2, 1024), 256>>>(
        (const __half*)p_h, (const __half*)p_wfc2, fc2_b,
        p_h2, 256, 1024, nullptr);

    // out = x1 + LN(h2)
    ln_add_kernel<false><<<MROWS / 8, 256>>>((const float*)p_x1, (const float*)p_h2,
                                             n2s, n2b, out, nullptr);
}

// round 11
// speedup vs baseline: 2.9608x; 1.1125x over previous
#include <cuda_runtime.h>
#include <cuda_fp16.h>
#include <cstdint>

// ---------------------------------------------------------------------------
// SwinV2 block: B=32, H=W=64, C=256, NH=8, HD=32, WS=8, SS=4
// Round 10: cp.async 3-stage GEMM pipeline + transposed-smem attention.
// ---------------------------------------------------------------------------

static constexpr int SSc   = 4;
static constexpr int NTOK  = 64;
static constexpr int NHc   = 8;
static constexpr int Cc    = 256;
static constexpr int MROWS = 131072;
static constexpr int HIDc  = 1024;

__device__ float  g_qkv [(size_t)MROWS * 768];     // fp32: attention input
__device__ __half g_attn[(size_t)MROWS * Cc];      // fp16: proj A input
__device__ float  g_y   [(size_t)MROWS * Cc];
__device__ float  g_x1  [(size_t)MROWS * Cc];      // fp32: residual
__device__ __half g_x1h [(size_t)MROWS * Cc];      // fp16 mirror: fc1 A input
__device__ __half g_h   [(size_t)MROWS * HIDc];    // fp16: fc2 A input
__device__ float  g_h2  [(size_t)MROWS * Cc];
__device__ __half g_xh  [(size_t)MROWS * Cc];      // fp16 gathered x: qkv A input
__device__ float  g_rpb [NHc * NTOK * NTOK];
__device__ float  g_qkvbias[768];
__device__ float  g_hscale[NHc];
__device__ int    g_rowmap[MROWS];
// fp16 weights, transposed to [N, K] K-major
__device__ __half g_wqkv_h[768 * 256];
__device__ __half g_wproj_h[256 * 256];
__device__ __half g_wfc1_h[1024 * 256];
__device__ __half g_wfc2_h[256 * 1024];

__device__ __forceinline__ float gelu_f(float x) {
    float x3 = x * x * x;
    return 0.5f * x * (1.f + tanhf(0.7978845608028654f * (x + 0.044715f * x3)));
}
__device__ __forceinline__ uint32_t smem_u32(const void* p) {
    uint32_t a;
    asm("{ .reg .u64 t; cvta.to.shared.u64 t, %1; cvt.u32.u64 %0, t; }" : "=r"(a) : "l"(p));
    return a;
}
__device__ __forceinline__ void mma_f16(float* c, const unsigned* a, const unsigned* b) {
    asm volatile(
        "mma.sync.aligned.m16n8k16.row.col.f32.f16.f16.f32 "
        "{%0,%1,%2,%3}, {%4,%5,%6,%7}, {%8,%9}, {%0,%1,%2,%3};"
        : "+f"(c[0]), "+f"(c[1]), "+f"(c[2]), "+f"(c[3])
        : "r"(a[0]), "r"(a[1]), "r"(a[2]), "r"(a[3]), "r"(b[0]), "r"(b[1]));
}
__device__ __forceinline__ void ldsm4(unsigned* r, uint32_t addr) {
    asm volatile("ldmatrix.sync.aligned.m8n8.x4.shared.b16 {%0,%1,%2,%3}, [%4];"
        : "=r"(r[0]), "=r"(r[1]), "=r"(r[2]), "=r"(r[3]) : "r"(addr));
}
__device__ __forceinline__ void cp16(uint32_t dst, const void* src) {
    asm volatile("cp.async.cg.shared.global [%0], [%1], 16;" :: "r"(dst), "l"(src));
}

// ---------------------------------------------------------------------------
__global__ void prep_kernel(const float* __restrict__ logit_scale,
                            const float* __restrict__ cpb_w1,
                            const float* __restrict__ cpb_b1,
                            const float* __restrict__ cpb_w2,
                            const float* __restrict__ q_bias,
                            const float* __restrict__ v_bias) {
    __shared__ float table[225][NHc];
    int t = threadIdx.x;
    for (int i = t; i < 768; i += 256) {
        float v = 0.f;
        if (i < 256)       v = q_bias[i];
        else if (i >= 512) v = v_bias[i - 512];
        g_qkvbias[i] = v;
    }
    if (t < NHc) {
        float ls = logit_scale[t];
        g_hscale[t] = expf(fminf(ls, 4.605170185988092f));
    }
    if (t < 225) {
        int a = t / 15, b = t % 15;
        float f0 = (float)(a - 7) * (8.f / 7.f);
        float f1 = (float)(b - 7) * (8.f / 7.f);
        f0 = copysignf(log2f(fabsf(f0) + 1.f) * (1.f / 3.f), f0);
        f1 = copysignf(log2f(fabsf(f1) + 1.f) * (1.f / 3.f), f1);
        float acc[NHc];
        #pragma unroll
        for (int h = 0; h < NHc; h++) acc[h] = 0.f;
        for (int j = 0; j < 512; j++) {
            float hid = f0 * cpb_w1[j] + f1 * cpb_w1[512 + j] + cpb_b1[j];
            hid = fmaxf(hid, 0.f);
            #pragma unroll
            for (int h = 0; h < NHc; h++) acc[h] += hid * cpb_w2[j * NHc + h];
        }
        #pragma unroll
        for (int h = 0; h < NHc; h++) table[t][h] = acc[h];
    }
    __syncthreads();
    for (int idx = t; idx < NHc * NTOK * NTOK; idx += 256) {
        int h = idx >> 12, rem = idx & 4095, i = rem >> 6, j = rem & 63;
        int iy = i >> 3, ix = i & 7, jy = j >> 3, jx = j & 7;
        int ti = (iy - jy + 7) * 15 + (ix - jx + 7);
        float v = table[ti][h];
        g_rpb[idx] = 16.f / (1.f + expf(-v));
    }
}

__global__ void rowmap_kernel() {
    int r = blockIdx.x * 256 + threadIdx.x;
    if (r >= MROWS) return;
    int b = r >> 12;
    int rem = r & 4095;
    int w = rem >> 6, n = rem & 63;
    int wy = w >> 3, wx = w & 7, ty = n >> 3, tx = n & 7;
    int hs = (wy * 8 + ty + SSc) & 63;
    int ws = (wx * 8 + tx + SSc) & 63;
    g_rowmap[r] = (b << 12) + (hs << 6) + ws;
}

// gathered fp16 copy of x
__global__ void xgather_kernel(const float* __restrict__ x) {
    int idx = blockIdx.x * 256 + threadIdx.x;
    int base = idx << 3;
    int row = base >> 8, col = base & 255;
    int b = row >> 12, rem = row & 4095;
    int w = rem >> 6, n = rem & 63;
    int wy = w >> 3, wx = w & 7, ty = n >> 3, tx = n & 7;
    int hs = (wy * 8 + ty + SSc) & 63;
    int ws = (wx * 8 + tx + SSc) & 63;
    int src = (b << 12) + (hs << 6) + ws;
    const float* p = x + (size_t)src * 256 + col;
    float4 f0 = *(const float4*)p;
    float4 f1 = *(const float4*)(p + 4);
    __half2 h0 = __floats2half2_rn(f0.x, f0.y);
    __half2 h1 = __floats2half2_rn(f0.z, f0.w);
    __half2 h2 = __floats2half2_rn(f1.x, f1.y);
    __half2 h3 = __floats2half2_rn(f1.z, f1.w);
    uint4 u;
    u.x = *(unsigned*)&h0; u.y = *(unsigned*)&h1;
    u.z = *(unsigned*)&h2; u.w = *(unsigned*)&h3;
    *(uint4*)(g_xh + (size_t)row * 256 + col) = u;
}

// Wt[n*K + k] = half(W[k*N + n])
__global__ void wtrans_kernel(const float* __restrict__ W, __half* __restrict__ Wt,
                              int K, int N) {
    int idx = blockIdx.x * 256 + threadIdx.x;
    if (idx >= K * N) return;
    int n = idx / K, k = idx - n * K;
    Wt[idx] = __float2half_rn(W[(size_t)k * N + n]);
}

// ---------------------------------------------------------------------------
// fp16 GEMM with 3-stage cp.async pipeline.
// A fp16 [M,K]; B fp16 [N,K] K-major. BM=BN=128, BK=16, 8 warps (2x4),
// warp tile 64x32. smem stride 24 halfs; ldmatrix.x4 fragment loads.
// ---------------------------------------------------------------------------
#define HS_STRIDE 24
#define STAGEB (128 * HS_STRIDE * 2)   // bytes per stage per array

template<bool GELU, bool SCATTER_C, bool OUT_HALF>
__global__ __launch_bounds__(256)
void gemm_f16(const __half* __restrict__ A, const __half* __restrict__ Bt,
              const float* __restrict__ bias, void* __restrict__ Cm,
              int N, int K, const int* __restrict__ rowmap) {
    __shared__ __align__(16) __half As[3][128 * HS_STRIDE];
    __shared__ __align__(16) __half Bs[3][128 * HS_STRIDE];

    const int t = threadIdx.x;
    const int lane = t & 31, wid = t >> 5;
    const int wm = (wid >> 2) << 6;
    const int wn = (wid & 3) << 5;
    const int m0 = blockIdx.y * 128, n0 = blockIdx.x * 128;

    // loader: row am (0..127), 8 halfs at ak -> one 16B cp.async each array
    const int am = t >> 1;
    const int ak = (t & 1) << 3;
    const __half* ap = A  + (size_t)(m0 + am) * K + ak;
    const __half* bp = Bt + (size_t)(n0 + am) * K + ak;
    const uint32_t a_dst = smem_u32(&As[0][am * HS_STRIDE + ak]);
    const uint32_t b_dst = smem_u32(&Bs[0][am * HS_STRIDE + ak]);

    // ldmatrix source addresses
    const int quad = lane >> 3, lr = lane & 7;
    const uint32_t a_addr0 = smem_u32(&As[0][(wm + ((quad & 1) << 3) + lr) * HS_STRIDE
                                             + ((quad >> 1) << 3)]);
    const uint32_t b_addr0 = smem_u32(&Bs[0][(wn + ((quad >> 1) << 3) + lr) * HS_STRIDE
                                             + ((quad & 1) << 3)]);
    const uint32_t MTB = 16 * HS_STRIDE * 2;

    float acc[4][4][4];
    #pragma unroll
    for (int i = 0; i < 4; i++)
        #pragma unroll
        for (int j = 0; j < 4; j++)
            #pragma unroll
            for (int r = 0; r < 4; r++) acc[i][j][r] = 0.f;

    const int KT = K >> 4;

    // prologue: stages 0 and 1
    cp16(a_dst, ap);
    cp16(b_dst, bp);
    asm volatile("cp.async.commit_group;" ::: "memory");
    cp16(a_dst + STAGEB, ap + 16);
    cp16(b_dst + STAGEB, bp + 16);
    asm volatile("cp.async.commit_group;" ::: "memory");

    int cur = 0;
    for (int kt = 0; kt < KT; kt++) {
        if (kt == KT - 1) asm volatile("cp.async.wait_group 0;" ::: "memory");
        else              asm volatile("cp.async.wait_group 1;" ::: "memory");
        __syncthreads();

        if (kt + 2 < KT) {
            int st = kt + 2;
            int sb = st - (st / 3) * 3;
            cp16(a_dst + sb * STAGEB, ap + st * 16);
            cp16(b_dst + sb * STAGEB, bp + st * 16);
            asm volatile("cp.async.commit_group;" ::: "memory");
        }

        unsigned afrag[4][4], bfrag[4][2];
        {
            const uint32_t ab = a_addr0 + cur * STAGEB;
            #pragma unroll
            for (int mt = 0; mt < 4; mt++) ldsm4(afrag[mt], ab + mt * MTB);
            const uint32_t bb = b_addr0 + cur * STAGEB;
            unsigned tmp[4];
            ldsm4(tmp, bb);
            bfrag[0][0] = tmp[0]; bfrag[0][1] = tmp[1];
            bfrag[1][0] = tmp[2]; bfrag[1][1] = tmp[3];
            ldsm4(tmp, bb + MTB);
            bfrag[2][0] = tmp[0]; bfrag[2][1] = tmp[1];
            bfrag[3][0] = tmp[2]; bfrag[3][1] = tmp[3];
        }
        #pragma unroll
        for (int mt = 0; mt < 4; mt++)
            #pragma unroll
            for (int nt = 0; nt < 4; nt++)
                mma_f16(acc[mt][nt], afrag[mt], bfrag[nt]);

        if (++cur == 3) cur = 0;
    }

    // epilogue
    float bv[4][2];
    #pragma unroll
    for (int nt = 0; nt < 4; nt++) {
        int c = n0 + wn + (nt << 3) + ((lane & 3) << 1);
        bv[nt][0] = bias[c];
        bv[nt][1] = bias[c + 1];
    }
    #pragma unroll
    for (int mt = 0; mt < 4; mt++) {
        int rr = m0 + wm + (mt << 4) + (lane >> 2);
        int r2 = rr + 8;
        int o1 = SCATTER_C ? rowmap[rr] : rr;
        int o2 = SCATTER_C ? rowmap[r2] : r2;
        #pragma unroll
        for (int nt = 0; nt < 4; nt++) {
            int c = n0 + wn + (nt << 3) + ((lane & 3) << 1);
            float2 v0, v1;
            v0.x = acc[mt][nt][0] + bv[nt][0];
            v0.y = acc[mt][nt][1] + bv[nt][1];
            v1.x = acc[mt][nt][2] + bv[nt][0];
            v1.y = acc[mt][nt][3] + bv[nt][1];
            if (GELU) {
                v0.x = gelu_f(v0.x); v0.y = gelu_f(v0.y);
                v1.x = gelu_f(v1.x); v1.y = gelu_f(v1.y);
            }
            if (OUT_HALF) {
                __half* C = (__half*)Cm;
                *(__half2*)(C + (size_t)o1 * N + c) = __floats2half2_rn(v0.x, v0.y);
                *(__half2*)(C + (size_t)o2 * N + c) = __floats2half2_rn(v1.x, v1.y);
            } else {
                float* C = (float*)Cm;
                *(float2*)(C + (size_t)o1 * N + c) = v0;
                *(float2*)(C + (size_t)o2 * N + c) = v1;
            }
        }
    }
}

// ---------------------------------------------------------------------------
// Windowed cosine attention: one block per (window, head). 256 threads.
// Q,K stored d-major (transposed) in smem -> S-loop uses LDS.128.
// ---------------------------------------------------------------------------
__global__ __launch_bounds__(256)
void attn_kernel(const float* __restrict__ qkv, __half* __restrict__ out) {
    __shared__ float qsT[32][68];   // [d][n]
    __shared__ float ksT[32][68];   // [d][n]
    __shared__ float vs[64][36];    // [n][d]
    __shared__ float Ss[64][68];
    __shared__ int lab[64];
    const int t  = threadIdx.x;
    const int b_ = blockIdx.x >> 3, h = blockIdx.x & 7;

    const float* base = qkv + (size_t)b_ * (64 * 768) + h * 32;
    #pragma unroll
    for (int r = 0; r < 2; r++) {
        int idx = r * 256 + t;              // 512 float4 loads per tensor
        int n = idx >> 3, d4 = (idx & 7) << 2;
        const float* p = base + n * 768 + d4;
        float4 q4 = *(const float4*)p;
        float4 k4 = *(const float4*)(p + 256);
        float4 v4 = *(const float4*)(p + 512);
        qsT[d4 + 0][n] = q4.x; qsT[d4 + 1][n] = q4.y;
        qsT[d4 + 2][n] = q4.z; qsT[d4 + 3][n] = q4.w;
        ksT[d4 + 0][n] = k4.x; ksT[d4 + 1][n] = k4.y;
        ksT[d4 + 2][n] = k4.z; ksT[d4 + 3][n] = k4.w;
        *(float4*)&vs[n][d4] = v4;
    }
    if (t < 64) {
        int w = b_ & 63;
        int wy = w >> 3, wx = w & 7, ty_ = t >> 3, tx_ = t & 7;
        int gh = wy * 8 + ty_, gw = wx * 8 + tx_;
        int rh = gh < 56 ? 0 : (gh < 60 ? 1 : 2);
        int rw = gw < 56 ? 0 : (gw < 60 ? 1 : 2);
        lab[t] = rh * 3 + rw;
    }
    __syncthreads();

    // L2-normalize q and k (4 lanes per token, 8 d each)
    {
        int row = t >> 2, sl = (t & 3) << 3;
        float s = 0.f;
        #pragma unroll
        for (int dd = 0; dd < 8; dd++) { float v = qsT[sl + dd][row]; s += v * v; }
        s += __shfl_xor_sync(0xffffffffu, s, 1);
        s += __shfl_xor_sync(0xffffffffu, s, 2);
        float rn = rsqrtf(fmaxf(s, 1e-12f));
        #pragma unroll
        for (int dd = 0; dd < 8; dd++) qsT[sl + dd][row] *= rn;
        s = 0.f;
        #pragma unroll
        for (int dd = 0; dd < 8; dd++) { float v = ksT[sl + dd][row]; s += v * v; }
        s += __shfl_xor_sync(0xffffffffu, s, 1);
        s += __shfl_xor_sync(0xffffffffu, s, 2);
        rn = rsqrtf(fmaxf(s, 1e-12f));
        #pragma unroll
        for (int dd = 0; dd < 8; dd++) ksT[sl + dd][row] *= rn;
    }
    __syncthreads();

    // S = qn @ knT * scale + rpb + mask  (4x4 tile; 2 LDS.128 per d)
    {
        const int i0 = (t >> 4) << 2, j0 = (t & 15) << 2;
        float accS[4][4];
        #pragma unroll
        for (int a = 0; a < 4; a++)
            #pragma unroll
            for (int b = 0; b < 4; b++) accS[a][b] = 0.f;
        #pragma unroll 4
        for (int d = 0; d < 32; d++) {
            float4 qa = *(const float4*)&qsT[d][i0];
            float4 kb = *(const float4*)&ksT[d][j0];
            float qv[4] = {qa.x, qa.y, qa.z, qa.w};
            float kv[4] = {kb.x, kb.y, kb.z, kb.w};
            #pragma unroll
            for (int a = 0; a < 4; a++)
                #pragma unroll
                for (int b = 0; b < 4; b++) accS[a][b] += qv[a] * kv[b];
        }
        const float sc = g_hscale[h];
        const float* rp = g_rpb + h * 4096;
        #pragma unroll
        for (int a = 0; a < 4; a++) {
            int i = i0 + a;
            float4 rv = *(const float4*)(rp + i * 64 + j0);
            float rr[4] = {rv.x, rv.y, rv.z, rv.w};
            float4 o;
            float* ov = (float*)&o;
            #pragma unroll
            for (int b = 0; b < 4; b++) {
                int j = j0 + b;
                float mval = (lab[i] == lab[j]) ? 0.f : -100.f;
                ov[b] = accS[a][b] * sc + rr[b] + mval;
            }
            *(float4*)&Ss[i][j0] = o;
        }
    }
    __syncthreads();

    // softmax per row (4 lanes per row, 16 cols each) with fast exp
    {
        int row = t >> 2, sl = (t & 3) << 4;
        float ev[16];
        float4 s0 = *(const float4*)&Ss[row][sl];
        float4 s1 = *(const float4*)&Ss[row][sl + 4];
        float4 s2 = *(const float4*)&Ss[row][sl + 8];
        float4 s3 = *(const float4*)&Ss[row][sl + 12];
        ev[0]=s0.x; ev[1]=s0.y; ev[2]=s0.z; ev[3]=s0.w;
        ev[4]=s1.x; ev[5]=s1.y; ev[6]=s1.z; ev[7]=s1.w;
        ev[8]=s2.x; ev[9]=s2.y; ev[10]=s2.z; ev[11]=s2.w;
        ev[12]=s3.x; ev[13]=s3.y; ev[14]=s3.z; ev[15]=s3.w;
        float mx = -1e30f;
        #pragma unroll
        for (int jj = 0; jj < 16; jj++) mx = fmaxf(mx, ev[jj]);
        mx = fmaxf(mx, __shfl_xor_sync(0xffffffffu, mx, 1));
        mx = fmaxf(mx, __shfl_xor_sync(0xffffffffu, mx, 2));
        float sm = 0.f;
        #pragma unroll
        for (int jj = 0; jj < 16; jj++) { ev[jj] = __expf(ev[jj] - mx); sm += ev[jj]; }
        sm += __shfl_xor_sync(0xffffffffu, sm, 1);
        sm += __shfl_xor_sync(0xffffffffu, sm, 2);
        float inv = 1.f / sm;
        #pragma unroll
        for (int jj = 0; jj < 16; jj++) ev[jj] *= inv;
        s0.x=ev[0]; s0.y=ev[1]; s0.z=ev[2]; s0.w=ev[3];
        s1.x=ev[4]; s1.y=ev[5]; s1.z=ev[6]; s1.w=ev[7];
        s2.x=ev[8]; s2.y=ev[9]; s2.z=ev[10]; s2.w=ev[11];
        s3.x=ev[12]; s3.y=ev[13]; s3.z=ev[14]; s3.w=ev[15];
        *(float4*)&Ss[row][sl]      = s0;
        *(float4*)&Ss[row][sl + 4]  = s1;
        *(float4*)&Ss[row][sl + 8]  = s2;
        *(float4*)&Ss[row][sl + 12] = s3;
    }
    __syncthreads();

    // O = P @ V : 2x4 tile per thread, LDS.128 on V
    {
        const int i0 = (t >> 3) << 1, d0 = (t & 7) << 2;
        float accO[2][4];
        #pragma unroll
        for (int a = 0; a < 2; a++)
            #pragma unroll
            for (int b = 0; b < 4; b++) accO[a][b] = 0.f;
        #pragma unroll 4
        for (int j = 0; j < 64; j++) {
            float pv0 = Ss[i0][j], pv1 = Ss[i0 + 1][j];
            float4 v4 = *(const float4*)&vs[j][d0];
            float vv[4] = {v4.x, v4.y, v4.z, v4.w};
            #pragma unroll
            for (int b = 0; b < 4; b++) {
                accO[0][b] += pv0 * vv[b];
                accO[1][b] += pv1 * vv[b];
            }
        }
        #pragma unroll
        for (int a = 0; a < 2; a++) {
            __half* op = out + (size_t)(b_ * 64 + i0 + a) * 256 + h * 32 + d0;
            *(__half2*)op       = __floats2half2_rn(accO[a][0], accO[a][1]);
            *(__half2*)(op + 2) = __floats2half2_rn(accO[a][2], accO[a][3]);
        }
    }
}

// ---------------------------------------------------------------------------
// out = resid + LayerNorm(y)*sc + bi ; optional fp16 mirror
// ---------------------------------------------------------------------------
template<bool WRITE_H>
__global__ __launch_bounds__(256)
void ln_add_kernel(const float* __restrict__ resid, const float* __restrict__ y,
                   const float* __restrict__ sc, const float* __restrict__ bi,
                   float* __restrict__ out, __half* __restrict__ outh) {
    int warp = (blockIdx.x * 256 + threadIdx.x) >> 5;
    int lane = threadIdx.x & 31;
    if (warp >= MROWS) return;
    const float* yr = y + (size_t)warp * 256;
    float v[8];
    #pragma unroll
    for (int i = 0; i < 8; i++) v[i] = yr[lane * 8 + i];
    float s = 0.f;
    #pragma unroll
    for (int i = 0; i < 8; i++) s += v[i];
    #pragma unroll
    for (int o = 16; o > 0; o >>= 1) s += __shfl_xor_sync(0xffffffffu, s, o);
    float mean = s * (1.f / 256.f);
    float sq = 0.f;
    #pragma unroll
    for (int i = 0; i < 8; i++) { float d = v[i] - mean; sq += d * d; }
    #pragma unroll
    for (int o = 16; o > 0; o >>= 1) sq += __shfl_xor_sync(0xffffffffu, sq, o);
    float rstd = rsqrtf(sq * (1.f / 256.f) + 1e-6f);
    const float* rr = resid + (size_t)warp * 256;
    float* op = out + (size_t)warp * 256;
    float ov[8];
    #pragma unroll
    for (int i = 0; i < 8; i++) {
        int c = lane * 8 + i;
        ov[i] = rr[c] + (v[i] - mean) * rstd * sc[c] + bi[c];
        op[c] = ov[i];
    }
    if (WRITE_H) {
        __half2 h0 = __floats2half2_rn(ov[0], ov[1]);
        __half2 h1 = __floats2half2_rn(ov[2], ov[3]);
        __half2 h2 = __floats2half2_rn(ov[4], ov[5]);
        __half2 h3 = __floats2half2_rn(ov[6], ov[7]);
        uint4 u;
        u.x = *(unsigned*)&h0; u.y = *(unsigned*)&h1;
        u.z = *(unsigned*)&h2; u.w = *(unsigned*)&h3;
        *(uint4*)(outh + (size_t)warp * 256 + lane * 8) = u;
    }
}

// ---------------------------------------------------------------------------
extern "C" void kernel_launch(void* const* d_in, const int* in_sizes, int n_in,
                              void* d_out, int out_size) {
    const float* x       = (const float*)d_in[0];
    const float* qkv_w   = (const float*)d_in[1];
    const float* q_bias  = (const float*)d_in[2];
    const float* v_bias  = (const float*)d_in[3];
    const float* lscale  = (const float*)d_in[4];
    const float* cpb_w1  = (const float*)d_in[5];
    const float* cpb_b1  = (const float*)d_in[6];
    const float* cpb_w2  = (const float*)d_in[7];
    const float* proj_w  = (const float*)d_in[8];
    const float* proj_b  = (const float*)d_in[9];
    const float* n1s     = (const float*)d_in[10];
    const float* n1b     = (const float*)d_in[11];
    const float* n2s     = (const float*)d_in[12];
    const float* n2b     = (const float*)d_in[13];
    const float* fc1_w   = (const float*)d_in[14];
    const float* fc1_b   = (const float*)d_in[15];
    const float* fc2_w   = (const float*)d_in[16];
    const float* fc2_b   = (const float*)d_in[17];
    float* out = (float*)d_out;

    void *p_qkv, *p_attn, *p_y, *p_x1, *p_x1h, *p_h, *p_h2, *p_xh, *p_qb, *p_rm;
    void *p_wqkv, *p_wproj, *p_wfc1, *p_wfc2;
    cudaGetSymbolAddress(&p_qkv,  g_qkv);
    cudaGetSymbolAddress(&p_attn, g_attn);
    cudaGetSymbolAddress(&p_y,    g_y);
    cudaGetSymbolAddress(&p_x1,   g_x1);
    cudaGetSymbolAddress(&p_x1h,  g_x1h);
    cudaGetSymbolAddress(&p_h,    g_h);
    cudaGetSymbolAddress(&p_h2,   g_h2);
    cudaGetSymbolAddress(&p_xh,   g_xh);
    cudaGetSymbolAddress(&p_qb,   g_qkvbias);
    cudaGetSymbolAddress(&p_rm,   g_rowmap);
    cudaGetSymbolAddress(&p_wqkv,  g_wqkv_h);
    cudaGetSymbolAddress(&p_wproj, g_wproj_h);
    cudaGetSymbolAddress(&p_wfc1,  g_wfc1_h);
    cudaGetSymbolAddress(&p_wfc2,  g_wfc2_h);

    prep_kernel<<<1, 256>>>(lscale, cpb_w1, cpb_b1, cpb_w2, q_bias, v_bias);
    rowmap_kernel<<<512, 256>>>();
    xgather_kernel<<<16384, 256>>>(x);
    wtrans_kernel<<<768,  256>>>(qkv_w,  (__half*)p_wqkv,  256, 768);
    wtrans_kernel<<<256,  256>>>(proj_w, (__half*)p_wproj, 256, 256);
    wtrans_kernel<<<1024, 256>>>(fc1_w,  (__half*)p_wfc1,  256, 1024);
    wtrans_kernel<<<1024, 256>>>(fc2_w,  (__half*)p_wfc2,  1024, 256);

    // qkv = xh @ qkv_w + qkv_bias
    gemm_f16<false, false, false><<<dim3(6, 1024), 256>>>(
        (const __half*)p_xh, (const __half*)p_wqkv, (const float*)p_qb,
        p_qkv, 768, 256, nullptr);

    attn_kernel<<<2048 * 8, 256>>>((const float*)p_qkv, (__half*)p_attn);

    // y = scatter(attn @ proj_w + proj_b)
    gemm_f16<false, true, false><<<dim3(2, 1024), 256>>>(
        (const __half*)p_attn, (const __half*)p_wproj, proj_b,
        p_y, 256, 256, (const int*)p_rm);

    // x1 = x + LN(y)
    ln_add_kernel<true><<<MROWS / 8, 256>>>(x, (const float*)p_y, n1s, n1b,
                                            (float*)p_x1, (__half*)p_x1h);

    // h = gelu(x1 @ fc1_w + fc1_b)
    gemm_f16<true, false, true><<<dim3(8, 1024), 256>>>(
        (const __half*)p_x1h, (const __half*)p_wfc1, fc1_b,
        p_h, 1024, 256, nullptr);

    // h2 = h @ fc2_w + fc2_b
    gemm_f16<false, false, false><<<dim3(2, 1024), 256>>>(
        (const __half*)p_h, (const __half*)p_wfc2, fc2_b,
        p_h2, 256, 1024, nullptr);

    // out = x1 + LN(h2)
    ln_add_kernel<false><<<MROWS / 8, 256>>>((const float*)p_x1, (const float*)p_h2,
                                             n2s, n2b, out, nullptr);
}

// round 12
// speedup vs baseline: 3.4302x; 1.1585x over previous
#include <cuda_runtime.h>
#include <cuda_fp16.h>
#include <cstdint>

// ---------------------------------------------------------------------------
// SwinV2 block: B=32, H=W=64, C=256, NH=8, HD=32, WS=8, SS=4
// Round 11: HMMA-tensorized attention (warp per window-head) + fp16 qkv.
// ---------------------------------------------------------------------------

static constexpr int SSc   = 4;
static constexpr int NTOK  = 64;
static constexpr int NHc   = 8;
static constexpr int Cc    = 256;
static constexpr int MROWS = 131072;
static constexpr int HIDc  = 1024;

__device__ __half g_qkvh[(size_t)MROWS * 768];     // fp16 qkv (GEMM out, attn in)
__device__ __half g_attn[(size_t)MROWS * Cc];      // fp16: proj A input
__device__ float  g_y   [(size_t)MROWS * Cc];
__device__ float  g_x1  [(size_t)MROWS * Cc];      // fp32: residual
__device__ __half g_x1h [(size_t)MROWS * Cc];      // fp16 mirror: fc1 A input
__device__ __half g_h   [(size_t)MROWS * HIDc];    // fp16: fc2 A input
__device__ float  g_h2  [(size_t)MROWS * Cc];
__device__ __half g_xh  [(size_t)MROWS * Cc];      // fp16 gathered x: qkv A input
__device__ float  g_rpb [NHc * NTOK * NTOK];
__device__ float  g_qkvbias[768];
__device__ float  g_hscale[NHc];
__device__ int    g_rowmap[MROWS];
__device__ __half g_wqkv_h[768 * 256];
__device__ __half g_wproj_h[256 * 256];
__device__ __half g_wfc1_h[1024 * 256];
__device__ __half g_wfc2_h[256 * 1024];

__device__ __forceinline__ float gelu_f(float x) {
    float x3 = x * x * x;
    return 0.5f * x * (1.f + tanhf(0.7978845608028654f * (x + 0.044715f * x3)));
}
__device__ __forceinline__ uint32_t smem_u32(const void* p) {
    uint32_t a;
    asm("{ .reg .u64 t; cvta.to.shared.u64 t, %1; cvt.u32.u64 %0, t; }" : "=r"(a) : "l"(p));
    return a;
}
__device__ __forceinline__ void mma_f16(float* c, const unsigned* a, const unsigned* b) {
    asm volatile(
        "mma.sync.aligned.m16n8k16.row.col.f32.f16.f16.f32 "
        "{%0,%1,%2,%3}, {%4,%5,%6,%7}, {%8,%9}, {%0,%1,%2,%3};"
        : "+f"(c[0]), "+f"(c[1]), "+f"(c[2]), "+f"(c[3])
        : "r"(a[0]), "r"(a[1]), "r"(a[2]), "r"(a[3]), "r"(b[0]), "r"(b[1]));
}
__device__ __forceinline__ void ldsm4(unsigned* r, uint32_t addr) {
    asm volatile("ldmatrix.sync.aligned.m8n8.x4.shared.b16 {%0,%1,%2,%3}, [%4];"
        : "=r"(r[0]), "=r"(r[1]), "=r"(r[2]), "=r"(r[3]) : "r"(addr));
}
__device__ __forceinline__ void ldsm4t(unsigned* r, uint32_t addr) {
    asm volatile("ldmatrix.sync.aligned.m8n8.x4.trans.shared.b16 {%0,%1,%2,%3}, [%4];"
        : "=r"(r[0]), "=r"(r[1]), "=r"(r[2]), "=r"(r[3]) : "r"(addr));
}
__device__ __forceinline__ void cp16(uint32_t dst, const void* src) {
    asm volatile("cp.async.cg.shared.global [%0], [%1], 16;" :: "r"(dst), "l"(src));
}
__device__ __forceinline__ unsigned pack_h2(float a, float b) {
    __half2 h = __floats2half2_rn(a, b);
    return *(unsigned*)&h;
}

// ---------------------------------------------------------------------------
__global__ void prep_kernel(const float* __restrict__ logit_scale,
                            const float* __restrict__ cpb_w1,
                            const float* __restrict__ cpb_b1,
                            const float* __restrict__ cpb_w2,
                            const float* __restrict__ q_bias,
                            const float* __restrict__ v_bias) {
    __shared__ float table[225][NHc];
    int t = threadIdx.x;
    for (int i = t; i < 768; i += 256) {
        float v = 0.f;
        if (i < 256)       v = q_bias[i];
        else if (i >= 512) v = v_bias[i - 512];
        g_qkvbias[i] = v;
    }
    if (t < NHc) {
        float ls = logit_scale[t];
        g_hscale[t] = expf(fminf(ls, 4.605170185988092f));
    }
    if (t < 225) {
        int a = t / 15, b = t % 15;
        float f0 = (float)(a - 7) * (8.f / 7.f);
        float f1 = (float)(b - 7) * (8.f / 7.f);
        f0 = copysignf(log2f(fabsf(f0) + 1.f) * (1.f / 3.f), f0);
        f1 = copysignf(log2f(fabsf(f1) + 1.f) * (1.f / 3.f), f1);
        float acc[NHc];
        #pragma unroll
        for (int h = 0; h < NHc; h++) acc[h] = 0.f;
        for (int j = 0; j < 512; j++) {
            float hid = f0 * cpb_w1[j] + f1 * cpb_w1[512 + j] + cpb_b1[j];
            hid = fmaxf(hid, 0.f);
            #pragma unroll
            for (int h = 0; h < NHc; h++) acc[h] += hid * cpb_w2[j * NHc + h];
        }
        #pragma unroll
        for (int h = 0; h < NHc; h++) table[t][h] = acc[h];
    }
    __syncthreads();
    for (int idx = t; idx < NHc * NTOK * NTOK; idx += 256) {
        int h = idx >> 12, rem = idx & 4095, i = rem >> 6, j = rem & 63;
        int iy = i >> 3, ix = i & 7, jy = j >> 3, jx = j & 7;
        int ti = (iy - jy + 7) * 15 + (ix - jx + 7);
        float v = table[ti][h];
        g_rpb[idx] = 16.f / (1.f + expf(-v));
    }
}

__global__ void rowmap_kernel() {
    int r = blockIdx.x * 256 + threadIdx.x;
    if (r >= MROWS) return;
    int b = r >> 12;
    int rem = r & 4095;
    int w = rem >> 6, n = rem & 63;
    int wy = w >> 3, wx = w & 7, ty = n >> 3, tx = n & 7;
    int hs = (wy * 8 + ty + SSc) & 63;
    int ws = (wx * 8 + tx + SSc) & 63;
    g_rowmap[r] = (b << 12) + (hs << 6) + ws;
}

__global__ void xgather_kernel(const float* __restrict__ x) {
    int idx = blockIdx.x * 256 + threadIdx.x;
    int base = idx << 3;
    int row = base >> 8, col = base & 255;
    int b = row >> 12, rem = row & 4095;
    int w = rem >> 6, n = rem & 63;
    int wy = w >> 3, wx = w & 7, ty = n >> 3, tx = n & 7;
    int hs = (wy * 8 + ty + SSc) & 63;
    int ws = (wx * 8 + tx + SSc) & 63;
    int src = (b << 12) + (hs << 6) + ws;
    const float* p = x + (size_t)src * 256 + col;
    float4 f0 = *(const float4*)p;
    float4 f1 = *(const float4*)(p + 4);
    uint4 u;
    u.x = pack_h2(f0.x, f0.y); u.y = pack_h2(f0.z, f0.w);
    u.z = pack_h2(f1.x, f1.y); u.w = pack_h2(f1.z, f1.w);
    *(uint4*)(g_xh + (size_t)row * 256 + col) = u;
}

__global__ void wtrans_kernel(const float* __restrict__ W, __half* __restrict__ Wt,
                              int K, int N) {
    int idx = blockIdx.x * 256 + threadIdx.x;
    if (idx >= K * N) return;
    int n = idx / K, k = idx - n * K;
    Wt[idx] = __float2half_rn(W[(size_t)k * N + n]);
}

// ---------------------------------------------------------------------------
// fp16 GEMM with 3-stage cp.async pipeline (unchanged from round 10).
// ---------------------------------------------------------------------------
#define HS_STRIDE 24
#define STAGEB (128 * HS_STRIDE * 2)

template<bool GELU, bool SCATTER_C, bool OUT_HALF>
__global__ __launch_bounds__(256)
void gemm_f16(const __half* __restrict__ A, const __half* __restrict__ Bt,
              const float* __restrict__ bias, void* __restrict__ Cm,
              int N, int K, const int* __restrict__ rowmap) {
    __shared__ __align__(16) __half As[3][128 * HS_STRIDE];
    __shared__ __align__(16) __half Bs[3][128 * HS_STRIDE];

    const int t = threadIdx.x;
    const int lane = t & 31, wid = t >> 5;
    const int wm = (wid >> 2) << 6;
    const int wn = (wid & 3) << 5;
    const int m0 = blockIdx.y * 128, n0 = blockIdx.x * 128;

    const int am = t >> 1;
    const int ak = (t & 1) << 3;
    const __half* ap = A  + (size_t)(m0 + am) * K + ak;
    const __half* bp = Bt + (size_t)(n0 + am) * K + ak;
    const uint32_t a_dst = smem_u32(&As[0][am * HS_STRIDE + ak]);
    const uint32_t b_dst = smem_u32(&Bs[0][am * HS_STRIDE + ak]);

    const int quad = lane >> 3, lr = lane & 7;
    const uint32_t a_addr0 = smem_u32(&As[0][(wm + ((quad & 1) << 3) + lr) * HS_STRIDE
                                             + ((quad >> 1) << 3)]);
    const uint32_t b_addr0 = smem_u32(&Bs[0][(wn + ((quad >> 1) << 3) + lr) * HS_STRIDE
                                             + ((quad & 1) << 3)]);
    const uint32_t MTB = 16 * HS_STRIDE * 2;

    float acc[4][4][4];
    #pragma unroll
    for (int i = 0; i < 4; i++)
        #pragma unroll
        for (int j = 0; j < 4; j++)
            #pragma unroll
            for (int r = 0; r < 4; r++) acc[i][j][r] = 0.f;

    const int KT = K >> 4;
    cp16(a_dst, ap);
    cp16(b_dst, bp);
    asm volatile("cp.async.commit_group;" ::: "memory");
    cp16(a_dst + STAGEB, ap + 16);
    cp16(b_dst + STAGEB, bp + 16);
    asm volatile("cp.async.commit_group;" ::: "memory");

    int cur = 0;
    for (int kt = 0; kt < KT; kt++) {
        if (kt == KT - 1) asm volatile("cp.async.wait_group 0;" ::: "memory");
        else              asm volatile("cp.async.wait_group 1;" ::: "memory");
        __syncthreads();

        if (kt + 2 < KT) {
            int st = kt + 2;
            int sb = st - (st / 3) * 3;
            cp16(a_dst + sb * STAGEB, ap + st * 16);
            cp16(b_dst + sb * STAGEB, bp + st * 16);
            asm volatile("cp.async.commit_group;" ::: "memory");
        }

        unsigned afrag[4][4], bfrag[4][2];
        {
            const uint32_t ab = a_addr0 + cur * STAGEB;
            #pragma unroll
            for (int mt = 0; mt < 4; mt++) ldsm4(afrag[mt], ab + mt * MTB);
            const uint32_t bb = b_addr0 + cur * STAGEB;
            unsigned tmp[4];
            ldsm4(tmp, bb);
            bfrag[0][0] = tmp[0]; bfrag[0][1] = tmp[1];
            bfrag[1][0] = tmp[2]; bfrag[1][1] = tmp[3];
            ldsm4(tmp, bb + MTB);
            bfrag[2][0] = tmp[0]; bfrag[2][1] = tmp[1];
            bfrag[3][0] = tmp[2]; bfrag[3][1] = tmp[3];
        }
        #pragma unroll
        for (int mt = 0; mt < 4; mt++)
            #pragma unroll
            for (int nt = 0; nt < 4; nt++)
                mma_f16(acc[mt][nt], afrag[mt], bfrag[nt]);

        if (++cur == 3) cur = 0;
    }

    float bv[4][2];
    #pragma unroll
    for (int nt = 0; nt < 4; nt++) {
        int c = n0 + wn + (nt << 3) + ((lane & 3) << 1);
        bv[nt][0] = bias[c];
        bv[nt][1] = bias[c + 1];
    }
    #pragma unroll
    for (int mt = 0; mt < 4; mt++) {
        int rr = m0 + wm + (mt << 4) + (lane >> 2);
        int r2 = rr + 8;
        int o1 = SCATTER_C ? rowmap[rr] : rr;
        int o2 = SCATTER_C ? rowmap[r2] : r2;
        #pragma unroll
        for (int nt = 0; nt < 4; nt++) {
            int c = n0 + wn + (nt << 3) + ((lane & 3) << 1);
            float2 v0, v1;
            v0.x = acc[mt][nt][0] + bv[nt][0];
            v0.y = acc[mt][nt][1] + bv[nt][1];
            v1.x = acc[mt][nt][2] + bv[nt][0];
            v1.y = acc[mt][nt][3] + bv[nt][1];
            if (GELU) {
                v0.x = gelu_f(v0.x); v0.y = gelu_f(v0.y);
                v1.x = gelu_f(v1.x); v1.y = gelu_f(v1.y);
            }
            if (OUT_HALF) {
                __half* C = (__half*)Cm;
                *(__half2*)(C + (size_t)o1 * N + c) = __floats2half2_rn(v0.x, v0.y);
                *(__half2*)(C + (size_t)o2 * N + c) = __floats2half2_rn(v1.x, v1.y);
            } else {
                float* C = (float*)Cm;
                *(float2*)(C + (size_t)o1 * N + c) = v0;
                *(float2*)(C + (size_t)o2 * N + c) = v1;
            }
        }
    }
}

// ---------------------------------------------------------------------------
// Tensorized windowed cosine attention.
// Block = 1 window (256 threads); warp h handles head h end-to-end.
// S = q@kT (HMMA, fp16 in / fp32 accum), scaled by invq*invk*logit_scale,
// +rpb +mask, fragment softmax, P@V (HMMA), fp16 out.
// ---------------------------------------------------------------------------
static constexpr int BLOB_STRIDE = 776;            // 768 + 8 pad (halfs)
static constexpr int SMEM_ATTN = 64 * BLOB_STRIDE * 2 + 2 * 8 * 64 * 4 + 64 * 4;

__global__ __launch_bounds__(256)
void attn_kernel(const __half* __restrict__ qkv, __half* __restrict__ out) {
    extern __shared__ __align__(16) unsigned char dynsm[];
    __half* blob   = (__half*)dynsm;                           // [64][776]
    float*  invq_s = (float*)(dynsm + 64 * BLOB_STRIDE * 2);   // [8][64]
    float*  invk_s = invq_s + 8 * 64;                          // [8][64]
    int*    lab    = (int*)(invk_s + 8 * 64);                  // [64]

    const int t = threadIdx.x, lane = t & 31, h = t >> 5;
    const int win = blockIdx.x;
    const __half* src = qkv + (size_t)win * 64 * 768;

    // stage window qkv into smem (fp16), 6144 16B chunks
    #pragma unroll
    for (int c = 0; c < 24; c++) {
        int chunk = c * 256 + t;
        int row = chunk / 96, off = (chunk - row * 96) << 3;
        cp16(smem_u32(blob + row * BLOB_STRIDE + off), src + row * 768 + off);
    }
    asm volatile("cp.async.commit_group;" ::: "memory");
    if (t < 64) {
        int w = win & 63;
        int wy = w >> 3, wx = w & 7, ty_ = t >> 3, tx_ = t & 7;
        int gh = wy * 8 + ty_, gw = wx * 8 + tx_;
        int rh = gh < 56 ? 0 : (gh < 60 ? 1 : 2);
        int rw = gw < 56 ? 0 : (gw < 60 ? 1 : 2);
        lab[t] = rh * 3 + rw;
    }
    asm volatile("cp.async.wait_group 0;" ::: "memory");
    __syncthreads();

    // fp32 norms of fp16 q,k rows (head h); 2 tokens per lane
    #pragma unroll
    for (int tk = lane; tk < 64; tk += 32) {
        const __half2* qp = (const __half2*)(blob + tk * BLOB_STRIDE + h * 32);
        const __half2* kp = (const __half2*)(blob + tk * BLOB_STRIDE + 256 + h * 32);
        float sq = 0.f, sk = 0.f;
        #pragma unroll
        for (int i = 0; i < 16; i++) {
            float2 f = __half22float2(qp[i]);
            sq += f.x * f.x + f.y * f.y;
            float2 g = __half22float2(kp[i]);
            sk += g.x * g.x + g.y * g.y;
        }
        invq_s[h * 64 + tk] = rsqrtf(fmaxf(sq, 1e-12f));
        invk_s[h * 64 + tk] = rsqrtf(fmaxf(sk, 1e-12f));
    }
    __syncwarp();

    const int quad = lane >> 3, lr = lane & 7;

    // A fragments (q): 4 mtiles x 2 ktiles
    unsigned aS[4][2][4];
    #pragma unroll
    for (int mt = 0; mt < 4; mt++)
        #pragma unroll
        for (int kt = 0; kt < 2; kt++) {
            int row = mt * 16 + ((quad & 1) << 3) + lr;
            int col = h * 32 + kt * 16 + ((quad >> 1) << 3);
            ldsm4(aS[mt][kt], smem_u32(blob + row * BLOB_STRIDE + col));
        }

    // S = q@kT
    float acc[4][8][4];
    #pragma unroll
    for (int mt = 0; mt < 4; mt++)
        #pragma unroll
        for (int nt = 0; nt < 8; nt++)
            #pragma unroll
            for (int r = 0; r < 4; r++) acc[mt][nt][r] = 0.f;
    #pragma unroll
    for (int np = 0; np < 4; np++)
        #pragma unroll
        for (int kt = 0; kt < 2; kt++) {
            int row = np * 16 + ((quad >> 1) << 3) + lr;
            int col = 256 + h * 32 + kt * 16 + ((quad & 1) << 3);
            unsigned bt[4];
            ldsm4(bt, smem_u32(blob + row * BLOB_STRIDE + col));
            #pragma unroll
            for (int mt = 0; mt < 4; mt++) {
                mma_f16(acc[mt][2 * np],     aS[mt][kt], bt);
                mma_f16(acc[mt][2 * np + 1], aS[mt][kt], bt + 2);
            }
        }

    // logits + softmax (per fragment row)
    const float sc = g_hscale[h];
    const float* rp = g_rpb + h * 4096;
    float ik0[8], ik1[8];
    int   cl0[8], cl1[8];
    #pragma unroll
    for (int nt = 0; nt < 8; nt++) {
        int c0 = nt * 8 + ((lane & 3) << 1);
        ik0[nt] = invk_s[h * 64 + c0];
        ik1[nt] = invk_s[h * 64 + c0 + 1];
        cl0[nt] = lab[c0];
        cl1[nt] = lab[c0 + 1];
    }
    #pragma unroll
    for (int mt = 0; mt < 4; mt++) {
        int r0 = mt * 16 + (lane >> 2), r1 = r0 + 8;
        float f0 = sc * invq_s[h * 64 + r0];
        float f1 = sc * invq_s[h * 64 + r1];
        int l0 = lab[r0], l1 = lab[r1];
        #pragma unroll
        for (int nt = 0; nt < 8; nt++) {
            int c0 = nt * 8 + ((lane & 3) << 1);
            float rp00 = __ldg(rp + r0 * 64 + c0), rp01 = __ldg(rp + r0 * 64 + c0 + 1);
            float rp10 = __ldg(rp + r1 * 64 + c0), rp11 = __ldg(rp + r1 * 64 + c0 + 1);
            acc[mt][nt][0] = acc[mt][nt][0] * f0 * ik0[nt] + rp00 + (l0 == cl0[nt] ? 0.f : -100.f);
            acc[mt][nt][1] = acc[mt][nt][1] * f0 * ik1[nt] + rp01 + (l0 == cl1[nt] ? 0.f : -100.f);
            acc[mt][nt][2] = acc[mt][nt][2] * f1 * ik0[nt] + rp10 + (l1 == cl0[nt] ? 0.f : -100.f);
            acc[mt][nt][3] = acc[mt][nt][3] * f1 * ik1[nt] + rp11 + (l1 == cl1[nt] ? 0.f : -100.f);
        }
        float m0 = -1e30f, m1 = -1e30f;
        #pragma unroll
        for (int nt = 0; nt < 8; nt++) {
            m0 = fmaxf(m0, fmaxf(acc[mt][nt][0], acc[mt][nt][1]));
            m1 = fmaxf(m1, fmaxf(acc[mt][nt][2], acc[mt][nt][3]));
        }
        m0 = fmaxf(m0, __shfl_xor_sync(0xffffffffu, m0, 1));
        m0 = fmaxf(m0, __shfl_xor_sync(0xffffffffu, m0, 2));
        m1 = fmaxf(m1, __shfl_xor_sync(0xffffffffu, m1, 1));
        m1 = fmaxf(m1, __shfl_xor_sync(0xffffffffu, m1, 2));
        float s0 = 0.f, s1 = 0.f;
        #pragma unroll
        for (int nt = 0; nt < 8; nt++) {
            acc[mt][nt][0] = __expf(acc[mt][nt][0] - m0); s0 += acc[mt][nt][0];
            acc[mt][nt][1] = __expf(acc[mt][nt][1] - m0); s0 += acc[mt][nt][1];
            acc[mt][nt][2] = __expf(acc[mt][nt][2] - m1); s1 += acc[mt][nt][2];
            acc[mt][nt][3] = __expf(acc[mt][nt][3] - m1); s1 += acc[mt][nt][3];
        }
        s0 += __shfl_xor_sync(0xffffffffu, s0, 1);
        s0 += __shfl_xor_sync(0xffffffffu, s0, 2);
        s1 += __shfl_xor_sync(0xffffffffu, s1, 1);
        s1 += __shfl_xor_sync(0xffffffffu, s1, 2);
        float i0 = 1.f / s0, i1 = 1.f / s1;
        #pragma unroll
        for (int nt = 0; nt < 8; nt++) {
            acc[mt][nt][0] *= i0; acc[mt][nt][1] *= i0;
            acc[mt][nt][2] *= i1; acc[mt][nt][3] *= i1;
        }
    }

    // P accum -> A fragments
    unsigned pf[4][4][4];
    #pragma unroll
    for (int mt = 0; mt < 4; mt++)
        #pragma unroll
        for (int kt = 0; kt < 4; kt++) {
            pf[mt][kt][0] = pack_h2(acc[mt][2 * kt][0],     acc[mt][2 * kt][1]);
            pf[mt][kt][1] = pack_h2(acc[mt][2 * kt][2],     acc[mt][2 * kt][3]);
            pf[mt][kt][2] = pack_h2(acc[mt][2 * kt + 1][0], acc[mt][2 * kt + 1][1]);
            pf[mt][kt][3] = pack_h2(acc[mt][2 * kt + 1][2], acc[mt][2 * kt + 1][3]);
        }

    // O = P@V  (V [token][d] via ldmatrix.trans as B)
    float O[4][4][4];
    #pragma unroll
    for (int mt = 0; mt < 4; mt++)
        #pragma unroll
        for (int nt = 0; nt < 4; nt++)
            #pragma unroll
            for (int r = 0; r < 4; r++) O[mt][nt][r] = 0.f;
    #pragma unroll
    for (int kt = 0; kt < 4; kt++)
        #pragma unroll
        for (int np = 0; np < 2; np++) {
            int row = kt * 16 + ((quad & 1) << 3) + lr;
            int col = 512 + h * 32 + np * 16 + ((quad >> 1) << 3);
            unsigned bt[4];
            ldsm4t(bt, smem_u32(blob + row * BLOB_STRIDE + col));
            #pragma unroll
            for (int mt = 0; mt < 4; mt++) {
                mma_f16(O[mt][2 * np],     pf[mt][kt], bt);
                mma_f16(O[mt][2 * np + 1], pf[mt][kt], bt + 2);
            }
        }

    // store fp16
    #pragma unroll
    for (int mt = 0; mt < 4; mt++) {
        int r0 = mt * 16 + (lane >> 2);
        #pragma unroll
        for (int nt = 0; nt < 4; nt++) {
            int c0 = nt * 8 + ((lane & 3) << 1);
            __half* op = out + (size_t)(win * 64 + r0) * 256 + h * 32 + c0;
            *(__half2*)op = __floats2half2_rn(O[mt][nt][0], O[mt][nt][1]);
            *(__half2*)(op + 8 * 256) = __floats2half2_rn(O[mt][nt][2], O[mt][nt][3]);
        }
    }
}

// ---------------------------------------------------------------------------
template<bool WRITE_H>
__global__ __launch_bounds__(256)
void ln_add_kernel(const float* __restrict__ resid, const float* __restrict__ y,
                   const float* __restrict__ sc, const float* __restrict__ bi,
                   float* __restrict__ out, __half* __restrict__ outh) {
    int warp = (blockIdx.x * 256 + threadIdx.x) >> 5;
    int lane = threadIdx.x & 31;
    if (warp >= MROWS) return;
    const float* yr = y + (size_t)warp * 256;
    float v[8];
    #pragma unroll
    for (int i = 0; i < 8; i++) v[i] = yr[lane * 8 + i];
    float s = 0.f;
    #pragma unroll
    for (int i = 0; i < 8; i++) s += v[i];
    #pragma unroll
    for (int o = 16; o > 0; o >>= 1) s += __shfl_xor_sync(0xffffffffu, s, o);
    float mean = s * (1.f / 256.f);
    float sq = 0.f;
    #pragma unroll
    for (int i = 0; i < 8; i++) { float d = v[i] - mean; sq += d * d; }
    #pragma unroll
    for (int o = 16; o > 0; o >>= 1) sq += __shfl_xor_sync(0xffffffffu, sq, o);
    float rstd = rsqrtf(sq * (1.f / 256.f) + 1e-6f);
    const float* rr = resid + (size_t)warp * 256;
    float* op = out + (size_t)warp * 256;
    float ov[8];
    #pragma unroll
    for (int i = 0; i < 8; i++) {
        int c = lane * 8 + i;
        ov[i] = rr[c] + (v[i] - mean) * rstd * sc[c] + bi[c];
        op[c] = ov[i];
    }
    if (WRITE_H) {
        uint4 u;
        u.x = pack_h2(ov[0], ov[1]); u.y = pack_h2(ov[2], ov[3]);
        u.z = pack_h2(ov[4], ov[5]); u.w = pack_h2(ov[6], ov[7]);
        *(uint4*)(outh + (size_t)warp * 256 + lane * 8) = u;
    }
}

// ---------------------------------------------------------------------------
extern "C" void kernel_launch(void* const* d_in, const int* in_sizes, int n_in,
                              void* d_out, int out_size) {
    const float* x       = (const float*)d_in[0];
    const float* qkv_w   = (const float*)d_in[1];
    const float* q_bias  = (const float*)d_in[2];
    const float* v_bias  = (const float*)d_in[3];
    const float* lscale  = (const float*)d_in[4];
    const float* cpb_w1  = (const float*)d_in[5];
    const float* cpb_b1  = (const float*)d_in[6];
    const float* cpb_w2  = (const float*)d_in[7];
    const float* proj_w  = (const float*)d_in[8];
    const float* proj_b  = (const float*)d_in[9];
    const float* n1s     = (const float*)d_in[10];
    const float* n1b     = (const float*)d_in[11];
    const float* n2s     = (const float*)d_in[12];
    const float* n2b     = (const float*)d_in[13];
    const float* fc1_w   = (const float*)d_in[14];
    const float* fc1_b   = (const float*)d_in[15];
    const float* fc2_w   = (const float*)d_in[16];
    const float* fc2_b   = (const float*)d_in[17];
    float* out = (float*)d_out;

    void *p_qkvh, *p_attn, *p_y, *p_x1, *p_x1h, *p_h, *p_h2, *p_xh, *p_qb, *p_rm;
    void *p_wqkv, *p_wproj, *p_wfc1, *p_wfc2;
    cudaGetSymbolAddress(&p_qkvh, g_qkvh);
    cudaGetSymbolAddress(&p_attn, g_attn);
    cudaGetSymbolAddress(&p_y,    g_y);
    cudaGetSymbolAddress(&p_x1,   g_x1);
    cudaGetSymbolAddress(&p_x1h,  g_x1h);
    cudaGetSymbolAddress(&p_h,    g_h);
    cudaGetSymbolAddress(&p_h2,   g_h2);
    cudaGetSymbolAddress(&p_xh,   g_xh);
    cudaGetSymbolAddress(&p_qb,   g_qkvbias);
    cudaGetSymbolAddress(&p_rm,   g_rowmap);
    cudaGetSymbolAddress(&p_wqkv,  g_wqkv_h);
    cudaGetSymbolAddress(&p_wproj, g_wproj_h);
    cudaGetSymbolAddress(&p_wfc1,  g_wfc1_h);
    cudaGetSymbolAddress(&p_wfc2,  g_wfc2_h);

    cudaFuncSetAttribute(attn_kernel, cudaFuncAttributeMaxDynamicSharedMemorySize,
                         SMEM_ATTN);

    prep_kernel<<<1, 256>>>(lscale, cpb_w1, cpb_b1, cpb_w2, q_bias, v_bias);
    rowmap_kernel<<<512, 256>>>();
    xgather_kernel<<<16384, 256>>>(x);
    wtrans_kernel<<<768,  256>>>(qkv_w,  (__half*)p_wqkv,  256, 768);
    wtrans_kernel<<<256,  256>>>(proj_w, (__half*)p_wproj, 256, 256);
    wtrans_kernel<<<1024, 256>>>(fc1_w,  (__half*)p_wfc1,  256, 1024);
    wtrans_kernel<<<1024, 256>>>(fc2_w,  (__half*)p_wfc2,  1024, 256);

    // qkv = xh @ qkv_w + qkv_bias  -> fp16
    gemm_f16<false, false, true><<<dim3(6, 1024), 256>>>(
        (const __half*)p_xh, (const __half*)p_wqkv, (const float*)p_qb,
        p_qkvh, 768, 256, nullptr);

    attn_kernel<<<2048, 256, SMEM_ATTN>>>((const __half*)p_qkvh, (__half*)p_attn);

    // y = scatter(attn @ proj_w + proj_b)
    gemm_f16<false, true, false><<<dim3(2, 1024), 256>>>(
        (const __half*)p_attn, (const __half*)p_wproj, proj_b,
        p_y, 256, 256, (const int*)p_rm);

    // x1 = x + LN(y)
    ln_add_kernel<true><<<MROWS / 8, 256>>>(x, (const float*)p_y, n1s, n1b,
                                            (float*)p_x1, (__half*)p_x1h);

    // h = gelu(x1 @ fc1_w + fc1_b)
    gemm_f16<true, false, true><<<dim3(8, 1024), 256>>>(
        (const __half*)p_x1h, (const __half*)p_wfc1, fc1_b,
        p_h, 1024, 256, nullptr);

    // h2 = h @ fc2_w + fc2_b
    gemm_f16<false, false, false><<<dim3(2, 1024), 256>>>(
        (const __half*)p_h, (const __half*)p_wfc2, fc2_b,
        p_h2, 256, 1024, nullptr);

    // out = x1 + LN(h2)
    ln_add_kernel<false><<<MROWS / 8, 256>>>((const float*)p_x1, (const float*)p_h2,
                                             n2s, n2b, out, nullptr);
}

// round 13
// speedup vs baseline: 3.4745x; 1.0129x over previous
#include <cuda_runtime.h>
#include <cuda_fp16.h>
#include <cstdint>

// ---------------------------------------------------------------------------
// SwinV2 block: B=32, H=W=64, C=256, NH=8, HD=32, WS=8, SS=4
// Round 13: BK=32 cp.async GEMM mainloop (half the barriers, 12:32 LDSM:MMA),
// HMMA-tensorized attention, fp16 intermediates.
// ---------------------------------------------------------------------------

static constexpr int SSc   = 4;
static constexpr int NTOK  = 64;
static constexpr int NHc   = 8;
static constexpr int Cc    = 256;
static constexpr int MROWS = 131072;
static constexpr int HIDc  = 1024;

__device__ __half g_qkvh[(size_t)MROWS * 768];
__device__ __half g_attn[(size_t)MROWS * Cc];
__device__ float  g_y   [(size_t)MROWS * Cc];
__device__ float  g_x1  [(size_t)MROWS * Cc];
__device__ __half g_x1h [(size_t)MROWS * Cc];
__device__ __half g_h   [(size_t)MROWS * HIDc];
__device__ float  g_h2  [(size_t)MROWS * Cc];
__device__ __half g_xh  [(size_t)MROWS * Cc];
__device__ float  g_rpb [NHc * NTOK * NTOK];
__device__ float  g_qkvbias[768];
__device__ float  g_hscale[NHc];
__device__ int    g_rowmap[MROWS];
__device__ __half g_wqkv_h[768 * 256];
__device__ __half g_wproj_h[256 * 256];
__device__ __half g_wfc1_h[1024 * 256];
__device__ __half g_wfc2_h[256 * 1024];

__device__ __forceinline__ float gelu_f(float x) {
    float x3 = x * x * x;
    return 0.5f * x * (1.f + tanhf(0.7978845608028654f * (x + 0.044715f * x3)));
}
__device__ __forceinline__ uint32_t smem_u32(const void* p) {
    uint32_t a;
    asm("{ .reg .u64 t; cvta.to.shared.u64 t, %1; cvt.u32.u64 %0, t; }" : "=r"(a) : "l"(p));
    return a;
}
__device__ __forceinline__ void mma_f16(float* c, const unsigned* a, const unsigned* b) {
    asm volatile(
        "mma.sync.aligned.m16n8k16.row.col.f32.f16.f16.f32 "
        "{%0,%1,%2,%3}, {%4,%5,%6,%7}, {%8,%9}, {%0,%1,%2,%3};"
        : "+f"(c[0]), "+f"(c[1]), "+f"(c[2]), "+f"(c[3])
        : "r"(a[0]), "r"(a[1]), "r"(a[2]), "r"(a[3]), "r"(b[0]), "r"(b[1]));
}
__device__ __forceinline__ void ldsm4(unsigned* r, uint32_t addr) {
    asm volatile("ldmatrix.sync.aligned.m8n8.x4.shared.b16 {%0,%1,%2,%3}, [%4];"
        : "=r"(r[0]), "=r"(r[1]), "=r"(r[2]), "=r"(r[3]) : "r"(addr));
}
__device__ __forceinline__ void ldsm4t(unsigned* r, uint32_t addr) {
    asm volatile("ldmatrix.sync.aligned.m8n8.x4.trans.shared.b16 {%0,%1,%2,%3}, [%4];"
        : "=r"(r[0]), "=r"(r[1]), "=r"(r[2]), "=r"(r[3]) : "r"(addr));
}
__device__ __forceinline__ void cp16(uint32_t dst, const void* src) {
    asm volatile("cp.async.cg.shared.global [%0], [%1], 16;" :: "r"(dst), "l"(src));
}
__device__ __forceinline__ unsigned pack_h2(float a, float b) {
    __half2 h = __floats2half2_rn(a, b);
    return *(unsigned*)&h;
}

// ---------------------------------------------------------------------------
__global__ void prep_kernel(const float* __restrict__ logit_scale,
                            const float* __restrict__ cpb_w1,
                            const float* __restrict__ cpb_b1,
                            const float* __restrict__ cpb_w2,
                            const float* __restrict__ q_bias,
                            const float* __restrict__ v_bias) {
    __shared__ float table[225][NHc];
    int t = threadIdx.x;
    for (int i = t; i < 768; i += 256) {
        float v = 0.f;
        if (i < 256)       v = q_bias[i];
        else if (i >= 512) v = v_bias[i - 512];
        g_qkvbias[i] = v;
    }
    if (t < NHc) {
        float ls = logit_scale[t];
        g_hscale[t] = expf(fminf(ls, 4.605170185988092f));
    }
    if (t < 225) {
        int a = t / 15, b = t % 15;
        float f0 = (float)(a - 7) * (8.f / 7.f);
        float f1 = (float)(b - 7) * (8.f / 7.f);
        f0 = copysignf(log2f(fabsf(f0) + 1.f) * (1.f / 3.f), f0);
        f1 = copysignf(log2f(fabsf(f1) + 1.f) * (1.f / 3.f), f1);
        float acc[NHc];
        #pragma unroll
        for (int h = 0; h < NHc; h++) acc[h] = 0.f;
        for (int j = 0; j < 512; j++) {
            float hid = f0 * cpb_w1[j] + f1 * cpb_w1[512 + j] + cpb_b1[j];
            hid = fmaxf(hid, 0.f);
            #pragma unroll
            for (int h = 0; h < NHc; h++) acc[h] += hid * cpb_w2[j * NHc + h];
        }
        #pragma unroll
        for (int h = 0; h < NHc; h++) table[t][h] = acc[h];
    }
    __syncthreads();
    for (int idx = t; idx < NHc * NTOK * NTOK; idx += 256) {
        int h = idx >> 12, rem = idx & 4095, i = rem >> 6, j = rem & 63;
        int iy = i >> 3, ix = i & 7, jy = j >> 3, jx = j & 7;
        int ti = (iy - jy + 7) * 15 + (ix - jx + 7);
        float v = table[ti][h];
        g_rpb[idx] = 16.f / (1.f + expf(-v));
    }
}

__global__ void rowmap_kernel() {
    int r = blockIdx.x * 256 + threadIdx.x;
    if (r >= MROWS) return;
    int b = r >> 12;
    int rem = r & 4095;
    int w = rem >> 6, n = rem & 63;
    int wy = w >> 3, wx = w & 7, ty = n >> 3, tx = n & 7;
    int hs = (wy * 8 + ty + SSc) & 63;
    int ws = (wx * 8 + tx + SSc) & 63;
    g_rowmap[r] = (b << 12) + (hs << 6) + ws;
}

__global__ void xgather_kernel(const float* __restrict__ x) {
    int idx = blockIdx.x * 256 + threadIdx.x;
    int base = idx << 3;
    int row = base >> 8, col = base & 255;
    int b = row >> 12, rem = row & 4095;
    int w = rem >> 6, n = rem & 63;
    int wy = w >> 3, wx = w & 7, ty = n >> 3, tx = n & 7;
    int hs = (wy * 8 + ty + SSc) & 63;
    int ws = (wx * 8 + tx + SSc) & 63;
    int src = (b << 12) + (hs << 6) + ws;
    const float* p = x + (size_t)src * 256 + col;
    float4 f0 = *(const float4*)p;
    float4 f1 = *(const float4*)(p + 4);
    uint4 u;
    u.x = pack_h2(f0.x, f0.y); u.y = pack_h2(f0.z, f0.w);
    u.z = pack_h2(f1.x, f1.y); u.w = pack_h2(f1.z, f1.w);
    *(uint4*)(g_xh + (size_t)row * 256 + col) = u;
}

__global__ void wtrans_kernel(const float* __restrict__ W, __half* __restrict__ Wt,
                              int K, int N) {
    int idx = blockIdx.x * 256 + threadIdx.x;
    if (idx >= K * N) return;
    int n = idx / K, k = idx - n * K;
    Wt[idx] = __float2half_rn(W[(size_t)k * N + n]);
}

// ---------------------------------------------------------------------------
// fp16 GEMM, BK=32, 3-stage cp.async pipeline.
// A fp16 [M,K]; B fp16 [N,K] K-major. BM=BN=128, 8 warps (2x4),
// warp tile 64x32. smem stride 40 halfs; ldmatrix.x4 fragment loads.
// ---------------------------------------------------------------------------
static constexpr int G_STRIDE = 40;                 // halfs per row
static constexpr int G_STAGEB = 128 * G_STRIDE * 2; // 10240 bytes / stage / array
static constexpr int SMEM_GEMM = 2 * 3 * G_STAGEB;  // 61440

template<bool GELU, bool SCATTER_C, bool OUT_HALF>
__global__ __launch_bounds__(256, 2)
void gemm_f16(const __half* __restrict__ A, const __half* __restrict__ Bt,
              const float* __restrict__ bias, void* __restrict__ Cm,
              int N, int K, const int* __restrict__ rowmap) {
    extern __shared__ __align__(16) unsigned char gsm[];
    __half* As = (__half*)gsm;                       // 3 stages
    __half* Bs = (__half*)(gsm + 3 * G_STAGEB);      // 3 stages

    const int t = threadIdx.x;
    const int lane = t & 31, wid = t >> 5;
    const int wm = (wid >> 2) << 6;
    const int wn = (wid & 3) << 5;
    const int m0 = blockIdx.y * 128, n0 = blockIdx.x * 128;

    // loader: row am (0..127), 16 halfs starting at ak (2 cp16 per array)
    const int am = t >> 1;
    const int ak = (t & 1) << 4;
    const __half* ap = A  + (size_t)(m0 + am) * K + ak;
    const __half* bp = Bt + (size_t)(n0 + am) * K + ak;
    const uint32_t a_dst = smem_u32(As + am * G_STRIDE + ak);
    const uint32_t b_dst = smem_u32(Bs + am * G_STRIDE + ak);

    const int quad = lane >> 3, lr = lane & 7;
    const uint32_t a_addr0 = smem_u32(As + (wm + ((quad & 1) << 3) + lr) * G_STRIDE
                                         + ((quad >> 1) << 3));
    const uint32_t b_addr0 = smem_u32(Bs + (wn + ((quad >> 1) << 3) + lr) * G_STRIDE
                                         + ((quad & 1) << 3));
    const uint32_t MTB = 16 * G_STRIDE * 2;          // 16 rows in bytes

    float acc[4][4][4];
    #pragma unroll
    for (int i = 0; i < 4; i++)
        #pragma unroll
        for (int j = 0; j < 4; j++)
            #pragma unroll
            for (int r = 0; r < 4; r++) acc[i][j][r] = 0.f;

    const int KT = K >> 5;   // BK=32

    // prologue: stages 0,1
    cp16(a_dst, ap);           cp16(a_dst + 16, ap + 8);
    cp16(b_dst, bp);           cp16(b_dst + 16, bp + 8);
    asm volatile("cp.async.commit_group;" ::: "memory");
    cp16(a_dst + G_STAGEB, ap + 32);  cp16(a_dst + G_STAGEB + 16, ap + 40);
    cp16(b_dst + G_STAGEB, bp + 32);  cp16(b_dst + G_STAGEB + 16, bp + 40);
    asm volatile("cp.async.commit_group;" ::: "memory");

    int cur = 0;
    for (int kt = 0; kt < KT; kt++) {
        if (kt == KT - 1) asm volatile("cp.async.wait_group 0;" ::: "memory");
        else              asm volatile("cp.async.wait_group 1;" ::: "memory");
        __syncthreads();

        if (kt + 2 < KT) {
            int st = kt + 2;
            int sb = st - (st / 3) * 3;
            const __half* asrc = ap + st * 32;
            const __half* bsrc = bp + st * 32;
            cp16(a_dst + sb * G_STAGEB, asrc);
            cp16(a_dst + sb * G_STAGEB + 16, asrc + 8);
            cp16(b_dst + sb * G_STAGEB, bsrc);
            cp16(b_dst + sb * G_STAGEB + 16, bsrc + 8);
            asm volatile("cp.async.commit_group;" ::: "memory");
        }

        #pragma unroll
        for (int ks = 0; ks < 2; ks++) {
            const uint32_t ab = a_addr0 + cur * G_STAGEB + ks * 32;
            const uint32_t bb = b_addr0 + cur * G_STAGEB + ks * 32;
            unsigned af[4][4], b0[4], b1[4];
            #pragma unroll
            for (int mt = 0; mt < 4; mt++) ldsm4(af[mt], ab + mt * MTB);
            ldsm4(b0, bb);
            ldsm4(b1, bb + MTB);
            #pragma unroll
            for (int mt = 0; mt < 4; mt++) {
                mma_f16(acc[mt][0], af[mt], b0);
                mma_f16(acc[mt][1], af[mt], b0 + 2);
                mma_f16(acc[mt][2], af[mt], b1);
                mma_f16(acc[mt][3], af[mt], b1 + 2);
            }
        }

        if (++cur == 3) cur = 0;
    }

    // epilogue
    float bv[4][2];
    #pragma unroll
    for (int nt = 0; nt < 4; nt++) {
        int c = n0 + wn + (nt << 3) + ((lane & 3) << 1);
        bv[nt][0] = bias[c];
        bv[nt][1] = bias[c + 1];
    }
    #pragma unroll
    for (int mt = 0; mt < 4; mt++) {
        int rr = m0 + wm + (mt << 4) + (lane >> 2);
        int r2 = rr + 8;
        int o1 = SCATTER_C ? rowmap[rr] : rr;
        int o2 = SCATTER_C ? rowmap[r2] : r2;
        #pragma unroll
        for (int nt = 0; nt < 4; nt++) {
            int c = n0 + wn + (nt << 3) + ((lane & 3) << 1);
            float2 v0, v1;
            v0.x = acc[mt][nt][0] + bv[nt][0];
            v0.y = acc[mt][nt][1] + bv[nt][1];
            v1.x = acc[mt][nt][2] + bv[nt][0];
            v1.y = acc[mt][nt][3] + bv[nt][1];
            if (GELU) {
                v0.x = gelu_f(v0.x); v0.y = gelu_f(v0.y);
                v1.x = gelu_f(v1.x); v1.y = gelu_f(v1.y);
            }
            if (OUT_HALF) {
                __half* C = (__half*)Cm;
                *(__half2*)(C + (size_t)o1 * N + c) = __floats2half2_rn(v0.x, v0.y);
                *(__half2*)(C + (size_t)o2 * N + c) = __floats2half2_rn(v1.x, v1.y);
            } else {
                float* C = (float*)Cm;
                *(float2*)(C + (size_t)o1 * N + c) = v0;
                *(float2*)(C + (size_t)o2 * N + c) = v1;
            }
        }
    }
}

// ---------------------------------------------------------------------------
// Tensorized windowed cosine attention (unchanged from round 12).
// ---------------------------------------------------------------------------
static constexpr int BLOB_STRIDE = 776;
static constexpr int SMEM_ATTN = 64 * BLOB_STRIDE * 2 + 2 * 8 * 64 * 4 + 64 * 4;

__global__ __launch_bounds__(256)
void attn_kernel(const __half* __restrict__ qkv, __half* __restrict__ out) {
    extern __shared__ __align__(16) unsigned char dynsm[];
    __half* blob   = (__half*)dynsm;
    float*  invq_s = (float*)(dynsm + 64 * BLOB_STRIDE * 2);
    float*  invk_s = invq_s + 8 * 64;
    int*    lab    = (int*)(invk_s + 8 * 64);

    const int t = threadIdx.x, lane = t & 31, h = t >> 5;
    const int win = blockIdx.x;
    const __half* src = qkv + (size_t)win * 64 * 768;

    #pragma unroll
    for (int c = 0; c < 24; c++) {
        int chunk = c * 256 + t;
        int row = chunk / 96, off = (chunk - row * 96) << 3;
        cp16(smem_u32(blob + row * BLOB_STRIDE + off), src + row * 768 + off);
    }
    asm volatile("cp.async.commit_group;" ::: "memory");
    if (t < 64) {
        int w = win & 63;
        int wy = w >> 3, wx = w & 7, ty_ = t >> 3, tx_ = t & 7;
        int gh = wy * 8 + ty_, gw = wx * 8 + tx_;
        int rh = gh < 56 ? 0 : (gh < 60 ? 1 : 2);
        int rw = gw < 56 ? 0 : (gw < 60 ? 1 : 2);
        lab[t] = rh * 3 + rw;
    }
    asm volatile("cp.async.wait_group 0;" ::: "memory");
    __syncthreads();

    #pragma unroll
    for (int tk = lane; tk < 64; tk += 32) {
        const __half2* qp = (const __half2*)(blob + tk * BLOB_STRIDE + h * 32);
        const __half2* kp = (const __half2*)(blob + tk * BLOB_STRIDE + 256 + h * 32);
        float sq = 0.f, sk = 0.f;
        #pragma unroll
        for (int i = 0; i < 16; i++) {
            float2 f = __half22float2(qp[i]);
            sq += f.x * f.x + f.y * f.y;
            float2 g = __half22float2(kp[i]);
            sk += g.x * g.x + g.y * g.y;
        }
        invq_s[h * 64 + tk] = rsqrtf(fmaxf(sq, 1e-12f));
        invk_s[h * 64 + tk] = rsqrtf(fmaxf(sk, 1e-12f));
    }
    __syncwarp();

    const int quad = lane >> 3, lr = lane & 7;

    unsigned aS[4][2][4];
    #pragma unroll
    for (int mt = 0; mt < 4; mt++)
        #pragma unroll
        for (int kt = 0; kt < 2; kt++) {
            int row = mt * 16 + ((quad & 1) << 3) + lr;
            int col = h * 32 + kt * 16 + ((quad >> 1) << 3);
            ldsm4(aS[mt][kt], smem_u32(blob + row * BLOB_STRIDE + col));
        }

    float acc[4][8][4];
    #pragma unroll
    for (int mt = 0; mt < 4; mt++)
        #pragma unroll
        for (int nt = 0; nt < 8; nt++)
            #pragma unroll
            for (int r = 0; r < 4; r++) acc[mt][nt][r] = 0.f;
    #pragma unroll
    for (int np = 0; np < 4; np++)
        #pragma unroll
        for (int kt = 0; kt < 2; kt++) {
            int row = np * 16 + ((quad >> 1) << 3) + lr;
            int col = 256 + h * 32 + kt * 16 + ((quad & 1) << 3);
            unsigned bt[4];
            ldsm4(bt, smem_u32(blob + row * BLOB_STRIDE + col));
            #pragma unroll
            for (int mt = 0; mt < 4; mt++) {
                mma_f16(acc[mt][2 * np],     aS[mt][kt], bt);
                mma_f16(acc[mt][2 * np + 1], aS[mt][kt], bt + 2);
            }
        }

    const float sc = g_hscale[h];
    const float* rp = g_rpb + h * 4096;
    float ik0[8], ik1[8];
    int   cl0[8], cl1[8];
    #pragma unroll
    for (int nt = 0; nt < 8; nt++) {
        int c0 = nt * 8 + ((lane & 3) << 1);
        ik0[nt] = invk_s[h * 64 + c0];
        ik1[nt] = invk_s[h * 64 + c0 + 1];
        cl0[nt] = lab[c0];
        cl1[nt] = lab[c0 + 1];
    }
    #pragma unroll
    for (int mt = 0; mt < 4; mt++) {
        int r0 = mt * 16 + (lane >> 2), r1 = r0 + 8;
        float f0 = sc * invq_s[h * 64 + r0];
        float f1 = sc * invq_s[h * 64 + r1];
        int l0 = lab[r0], l1 = lab[r1];
        #pragma unroll
        for (int nt = 0; nt < 8; nt++) {
            int c0 = nt * 8 + ((lane & 3) << 1);
            float rp00 = __ldg(rp + r0 * 64 + c0), rp01 = __ldg(rp + r0 * 64 + c0 + 1);
            float rp10 = __ldg(rp + r1 * 64 + c0), rp11 = __ldg(rp + r1 * 64 + c0 + 1);
            acc[mt][nt][0] = acc[mt][nt][0] * f0 * ik0[nt] + rp00 + (l0 == cl0[nt] ? 0.f : -100.f);
            acc[mt][nt][1] = acc[mt][nt][1] * f0 * ik1[nt] + rp01 + (l0 == cl1[nt] ? 0.f : -100.f);
            acc[mt][nt][2] = acc[mt][nt][2] * f1 * ik0[nt] + rp10 + (l1 == cl0[nt] ? 0.f : -100.f);
            acc[mt][nt][3] = acc[mt][nt][3] * f1 * ik1[nt] + rp11 + (l1 == cl1[nt] ? 0.f : -100.f);
        }
        float m0 = -1e30f, m1 = -1e30f;
        #pragma unroll
        for (int nt = 0; nt < 8; nt++) {
            m0 = fmaxf(m0, fmaxf(acc[mt][nt][0], acc[mt][nt][1]));
            m1 = fmaxf(m1, fmaxf(acc[mt][nt][2], acc[mt][nt][3]));
        }
        m0 = fmaxf(m0, __shfl_xor_sync(0xffffffffu, m0, 1));
        m0 = fmaxf(m0, __shfl_xor_sync(0xffffffffu, m0, 2));
        m1 = fmaxf(m1, __shfl_xor_sync(0xffffffffu, m1, 1));
        m1 = fmaxf(m1, __shfl_xor_sync(0xffffffffu, m1, 2));
        float s0 = 0.f, s1 = 0.f;
        #pragma unroll
        for (int nt = 0; nt < 8; nt++) {
            acc[mt][nt][0] = __expf(acc[mt][nt][0] - m0); s0 += acc[mt][nt][0];
            acc[mt][nt][1] = __expf(acc[mt][nt][1] - m0); s0 += acc[mt][nt][1];
            acc[mt][nt][2] = __expf(acc[mt][nt][2] - m1); s1 += acc[mt][nt][2];
            acc[mt][nt][3] = __expf(acc[mt][nt][3] - m1); s1 += acc[mt][nt][3];
        }
        s0 += __shfl_xor_sync(0xffffffffu, s0, 1);
        s0 += __shfl_xor_sync(0xffffffffu, s0, 2);
        s1 += __shfl_xor_sync(0xffffffffu, s1, 1);
        s1 += __shfl_xor_sync(0xffffffffu, s1, 2);
        float i0 = 1.f / s0, i1 = 1.f / s1;
        #pragma unroll
        for (int nt = 0; nt < 8; nt++) {
            acc[mt][nt][0] *= i0; acc[mt][nt][1] *= i0;
            acc[mt][nt][2] *= i1; acc[mt][nt][3] *= i1;
        }
    }

    unsigned pf[4][4][4];
    #pragma unroll
    for (int mt = 0; mt < 4; mt++)
        #pragma unroll
        for (int kt = 0; kt < 4; kt++) {
            pf[mt][kt][0] = pack_h2(acc[mt][2 * kt][0],     acc[mt][2 * kt][1]);
            pf[mt][kt][1] = pack_h2(acc[mt][2 * kt][2],     acc[mt][2 * kt][3]);
            pf[mt][kt][2] = pack_h2(acc[mt][2 * kt + 1][0], acc[mt][2 * kt + 1][1]);
            pf[mt][kt][3] = pack_h2(acc[mt][2 * kt + 1][2], acc[mt][2 * kt + 1][3]);
        }

    float O[4][4][4];
    #pragma unroll
    for (int mt = 0; mt < 4; mt++)
        #pragma unroll
        for (int nt = 0; nt < 4; nt++)
            #pragma unroll
            for (int r = 0; r < 4; r++) O[mt][nt][r] = 0.f;
    #pragma unroll
    for (int kt = 0; kt < 4; kt++)
        #pragma unroll
        for (int np = 0; np < 2; np++) {
            int row = kt * 16 + ((quad & 1) << 3) + lr;
            int col = 512 + h * 32 + np * 16 + ((quad >> 1) << 3);
            unsigned bt[4];
            ldsm4t(bt, smem_u32(blob + row * BLOB_STRIDE + col));
            #pragma unroll
            for (int mt = 0; mt < 4; mt++) {
                mma_f16(O[mt][2 * np],     pf[mt][kt], bt);
                mma_f16(O[mt][2 * np + 1], pf[mt][kt], bt + 2);
            }
        }

    #pragma unroll
    for (int mt = 0; mt < 4; mt++) {
        int r0 = mt * 16 + (lane >> 2);
        #pragma unroll
        for (int nt = 0; nt < 4; nt++) {
            int c0 = nt * 8 + ((lane & 3) << 1);
            __half* op = out + (size_t)(win * 64 + r0) * 256 + h * 32 + c0;
            *(__half2*)op = __floats2half2_rn(O[mt][nt][0], O[mt][nt][1]);
            *(__half2*)(op + 8 * 256) = __floats2half2_rn(O[mt][nt][2], O[mt][nt][3]);
        }
    }
}

// ---------------------------------------------------------------------------
template<bool WRITE_H>
__global__ __launch_bounds__(256)
void ln_add_kernel(const float* __restrict__ resid, const float* __restrict__ y,
                   const float* __restrict__ sc, const float* __restrict__ bi,
                   float* __restrict__ out, __half* __restrict__ outh) {
    int warp = (blockIdx.x * 256 + threadIdx.x) >> 5;
    int lane = threadIdx.x & 31;
    if (warp >= MROWS) return;
    const float* yr = y + (size_t)warp * 256;
    float v[8];
    #pragma unroll
    for (int i = 0; i < 8; i++) v[i] = yr[lane * 8 + i];
    float s = 0.f;
    #pragma unroll
    for (int i = 0; i < 8; i++) s += v[i];
    #pragma unroll
    for (int o = 16; o > 0; o >>= 1) s += __shfl_xor_sync(0xffffffffu, s, o);
    float mean = s * (1.f / 256.f);
    float sq = 0.f;
    #pragma unroll
    for (int i = 0; i < 8; i++) { float d = v[i] - mean; sq += d * d; }
    #pragma unroll
    for (int o = 16; o > 0; o >>= 1) sq += __shfl_xor_sync(0xffffffffu, sq, o);
    float rstd = rsqrtf(sq * (1.f / 256.f) + 1e-6f);
    const float* rr = resid + (size_t)warp * 256;
    float* op = out + (size_t)warp * 256;
    float ov[8];
    #pragma unroll
    for (int i = 0; i < 8; i++) {
        int c = lane * 8 + i;
        ov[i] = rr[c] + (v[i] - mean) * rstd * sc[c] + bi[c];
        op[c] = ov[i];
    }
    if (WRITE_H) {
        uint4 u;
        u.x = pack_h2(ov[0], ov[1]); u.y = pack_h2(ov[2], ov[3]);
        u.z = pack_h2(ov[4], ov[5]); u.w = pack_h2(ov[6], ov[7]);
        *(uint4*)(outh + (size_t)warp * 256 + lane * 8) = u;
    }
}

// ---------------------------------------------------------------------------
extern "C" void kernel_launch(void* const* d_in, const int* in_sizes, int n_in,
                              void* d_out, int out_size) {
    const float* x       = (const float*)d_in[0];
    const float* qkv_w   = (const float*)d_in[1];
    const float* q_bias  = (const float*)d_in[2];
    const float* v_bias  = (const float*)d_in[3];
    const float* lscale  = (const float*)d_in[4];
    const float* cpb_w1  = (const float*)d_in[5];
    const float* cpb_b1  = (const float*)d_in[6];
    const float* cpb_w2  = (const float*)d_in[7];
    const float* proj_w  = (const float*)d_in[8];
    const float* proj_b  = (const float*)d_in[9];
    const float* n1s     = (const float*)d_in[10];
    const float* n1b     = (const float*)d_in[11];
    const float* n2s     = (const float*)d_in[12];
    const float* n2b     = (const float*)d_in[13];
    const float* fc1_w   = (const float*)d_in[14];
    const float* fc1_b   = (const float*)d_in[15];
    const float* fc2_w   = (const float*)d_in[16];
    const float* fc2_b   = (const float*)d_in[17];
    float* out = (float*)d_out;

    void *p_qkvh, *p_attn, *p_y, *p_x1, *p_x1h, *p_h, *p_h2, *p_xh, *p_qb, *p_rm;
    void *p_wqkv, *p_wproj, *p_wfc1, *p_wfc2;
    cudaGetSymbolAddress(&p_qkvh, g_qkvh);
    cudaGetSymbolAddress(&p_attn, g_attn);
    cudaGetSymbolAddress(&p_y,    g_y);
    cudaGetSymbolAddress(&p_x1,   g_x1);
    cudaGetSymbolAddress(&p_x1h,  g_x1h);
    cudaGetSymbolAddress(&p_h,    g_h);
    cudaGetSymbolAddress(&p_h2,   g_h2);
    cudaGetSymbolAddress(&p_xh,   g_xh);
    cudaGetSymbolAddress(&p_qb,   g_qkvbias);
    cudaGetSymbolAddress(&p_rm,   g_rowmap);
    cudaGetSymbolAddress(&p_wqkv,  g_wqkv_h);
    cudaGetSymbolAddress(&p_wproj, g_wproj_h);
    cudaGetSymbolAddress(&p_wfc1,  g_wfc1_h);
    cudaGetSymbolAddress(&p_wfc2,  g_wfc2_h);

    cudaFuncSetAttribute(attn_kernel, cudaFuncAttributeMaxDynamicSharedMemorySize,
                         SMEM_ATTN);
    cudaFuncSetAttribute(gemm_f16<false, false, true>,
                         cudaFuncAttributeMaxDynamicSharedMemorySize, SMEM_GEMM);
    cudaFuncSetAttribute(gemm_f16<false, true, false>,
                         cudaFuncAttributeMaxDynamicSharedMemorySize, SMEM_GEMM);
    cudaFuncSetAttribute(gemm_f16<true, false, true>,
                         cudaFuncAttributeMaxDynamicSharedMemorySize, SMEM_GEMM);
    cudaFuncSetAttribute(gemm_f16<false, false, false>,
                         cudaFuncAttributeMaxDynamicSharedMemorySize, SMEM_GEMM);

    prep_kernel<<<1, 256>>>(lscale, cpb_w1, cpb_b1, cpb_w2, q_bias, v_bias);
    rowmap_kernel<<<512, 256>>>();
    xgather_kernel<<<16384, 256>>>(x);
    wtrans_kernel<<<768,  256>>>(qkv_w,  (__half*)p_wqkv,  256, 768);
    wtrans_kernel<<<256,  256>>>(proj_w, (__half*)p_wproj, 256, 256);
    wtrans_kernel<<<1024, 256>>>(fc1_w,  (__half*)p_wfc1,  256, 1024);
    wtrans_kernel<<<1024, 256>>>(fc2_w,  (__half*)p_wfc2,  1024, 256);

    // qkv = xh @ qkv_w + qkv_bias  -> fp16
    gemm_f16<false, false, true><<<dim3(6, 1024), 256, SMEM_GEMM>>>(
        (const __half*)p_xh, (const __half*)p_wqkv, (const float*)p_qb,
        p_qkvh, 768, 256, nullptr);

    attn_kernel<<<2048, 256, SMEM_ATTN>>>((const __half*)p_qkvh, (__half*)p_attn);

    // y = scatter(attn @ proj_w + proj_b)
    gemm_f16<false, true, false><<<dim3(2, 1024), 256, SMEM_GEMM>>>(
        (const __half*)p_attn, (const __half*)p_wproj, proj_b,
        p_y, 256, 256, (const int*)p_rm);

    // x1 = x + LN(y)
    ln_add_kernel<true><<<MROWS / 8, 256>>>(x, (const float*)p_y, n1s, n1b,
                                            (float*)p_x1, (__half*)p_x1h);

    // h = gelu(x1 @ fc1_w + fc1_b)
    gemm_f16<true, false, true><<<dim3(8, 1024), 256, SMEM_GEMM>>>(
        (const __half*)p_x1h, (const __half*)p_wfc1, fc1_b,
        p_h, 1024, 256, nullptr);

    // h2 = h @ fc2_w + fc2_b
    gemm_f16<false, false, false><<<dim3(2, 1024), 256, SMEM_GEMM>>>(
        (const __half*)p_h, (const __half*)p_wfc2, fc2_b,
        p_h2, 256, 1024, nullptr);

    // out = x1 + LN(h2)
    ln_add_kernel<false><<<MROWS / 8, 256>>>((const float*)p_x1, (const float*)p_h2,
                                             n2s, n2b, out, nullptr);
}